// round 8
// baseline (speedup 1.0000x reference)
#include <cuda_runtime.h>
#include <mma.h>
#include <cuda_bf16.h>
#include <cstdint>
#include <math.h>

using namespace nvcuda;
typedef __nv_bfloat16 bf16;

// ---------------- problem dims ----------------
#define Bn 64
#define Nn 256
#define Fn 16
#define Hn 256
#define ROWS (Bn*Nn)          // 16384
#define N_ITERS 10
#define PLANE (ROWS*Hn)       // 4194304

// ---------------- scratch ----------------
__device__ float g_h  [PLANE];
__device__ float g_z  [PLANE];
__device__ float g_jcz[PLANE];
__device__ float g_jcr[PLANE];
__device__ float g_jch[PLANE];
__device__ float g_t2 [PLANE];
__device__ bf16 g_hP [2*PLANE];
__device__ bf16 g_tP [2*PLANE];
__device__ bf16 g_mP [2*PLANE];
__device__ bf16 g_rhP[2*PLANE];
__device__ bf16 g_daP[2*PLANE];
#define WOFF_MSG 0
#define WOFF_ZR  65536
#define WOFF_HB  327680
#define WOFF_R1  458752
#define WOFF_R2  524288
#define WTOTAL   589824
__device__ bf16 g_wH[WTOTAL];
__device__ bf16 g_wL[WTOTAL];

__device__ __forceinline__ float sigf(float x) { return 1.0f / (1.0f + expf(-x)); }

__device__ __forceinline__ uint32_t smem_u32(const void* p) {
    return (uint32_t)__cvta_generic_to_shared(p);
}
#define CP16(dst, src) asm volatile("cp.async.cg.shared.global [%0], [%1], 16;" :: "r"(dst), "l"(src))
#define CP_COMMIT()    asm volatile("cp.async.commit_group;" ::: "memory")
#define CP_WAIT(n)     asm volatile("cp.async.wait_group %0;" :: "n"(n) : "memory")

__device__ __forceinline__ void split1(float v, bf16& h, bf16& l) {
    h = __float2bfloat16(v);
    l = __float2bfloat16(v - __bfloat162float(h));
}
__device__ __forceinline__ void store_planes(bf16* Ph, bf16* Pl, size_t idx, float4 v) {
    __nv_bfloat162 h01 = __floats2bfloat162_rn(v.x, v.y);
    __nv_bfloat162 h23 = __floats2bfloat162_rn(v.z, v.w);
    float r0 = v.x - __low2float(h01), r1 = v.y - __high2float(h01);
    float r2 = v.z - __low2float(h23), r3 = v.w - __high2float(h23);
    __nv_bfloat162 l01 = __floats2bfloat162_rn(r0, r1);
    __nv_bfloat162 l23 = __floats2bfloat162_rn(r2, r3);
    uint2 hv, lv;
    hv.x = *(uint32_t*)&h01; hv.y = *(uint32_t*)&h23;
    lv.x = *(uint32_t*)&l01; lv.y = *(uint32_t*)&l23;
    *(uint2*)(Ph + idx) = hv;
    *(uint2*)(Pl + idx) = lv;
}

// ---------------- GEMM: 128x256 block tile, warp tile 64x64 ----------------
enum { EPI_T = 0, EPI_M, EPI_ZR, EPI_GRU, EPI_R1, EPI_R2 };

#define STAGES 3
#define LDA 40                  // bf16, 80B rows
#define LDB 264                 // 256+8 bf16, 528B rows
#define A_BYTES (128*LDA*2)     // 10240 per plane
#define B_BYTES (32*LDB*2)      // 16896 per plane
#define AHI_OFF 0
#define ALO_OFF (A_BYTES)
#define BHI_OFF (2*A_BYTES)
#define BLO_OFF (2*A_BYTES + B_BYTES)
#define STAGE_BYTES (2*A_BYTES + 2*B_BYTES)   // 54272
#define SMEM_BYTES (STAGES*STAGE_BYTES)       // 162816 (>= 128KB C staging)

template<int EPI>
__global__ void __launch_bounds__(256, 1)
tc_gemm(const bf16* __restrict__ A0h, const bf16* __restrict__ A0l,
        const bf16* __restrict__ A1h, const bf16* __restrict__ A1l,
        const bf16* __restrict__ Bh,  const bf16* __restrict__ Bl,
        int NB, int K, int batched,
        const float* __restrict__ bias,
        const float* __restrict__ jc,  const float* __restrict__ jc2,
        const float* __restrict__ Hb,  const float* __restrict__ Zb,
        float* Cf, bf16* Ch, bf16* Cl)
{
    extern __shared__ char sm[];
    const uint32_t smaddr = smem_u32(sm);

    const int tid = threadIdx.x, wid = tid >> 5;
    const int bn = blockIdx.x * 256, bm = blockIdx.y * 128;
    const int warp_m = wid >> 2;        // 0..1 -> 64 rows
    const int warp_n = wid & 3;         // 0..3 -> 64 cols

    int am = bm;
    size_t aoff = 0, boff = 0;
    if (batched) {
        const int b = bm >> 8;
        aoff = (size_t)b * (Nn * Hn);
        boff = (size_t)b * (Nn * Hn);
        am = bm & (Nn - 1);
    }

    const int NC = K >> 5;

    auto issue = [&](int kb) {
        const int buf = kb % STAGES;
        const uint32_t sb = smaddr + buf * STAGE_BYTES;
        const int kk = (kb & 7) * 32;
        const bf16 *ah, *al; int arow;
        if (kb < 8) { ah = A0h + aoff; al = A0l + aoff; arow = am; }
        else        { ah = A1h;        al = A1l;        arow = bm; }
        // A: 128x32 bf16, 2 planes: 512 16B-chunks per plane
        #pragma unroll
        for (int i = 0; i < 2; i++) {
            const int c = tid + i * 256;
            const int r = c >> 2, c8 = (c & 3) * 8;
            const bf16* s1 = ah + (size_t)(arow + r) * Hn + kk + c8;
            const bf16* s2 = al + (size_t)(arow + r) * Hn + kk + c8;
            const uint32_t d = sb + AHI_OFF + (uint32_t)(r * LDA + c8) * 2;
            CP16(d, s1);
            CP16(d + (ALO_OFF - AHI_OFF), s2);
        }
        // B: 32x256 bf16, 2 planes: 1024 16B-chunks per plane
        #pragma unroll
        for (int i = 0; i < 4; i++) {
            const int c = tid + i * 256;
            const int r = c >> 5, c8 = (c & 31) * 8;
            const bf16* s1 = Bh + boff + (size_t)(kb * 32 + r) * NB + bn + c8;
            const bf16* s2 = Bl + boff + (size_t)(kb * 32 + r) * NB + bn + c8;
            const uint32_t d = sb + BHI_OFF + (uint32_t)(r * LDB + c8) * 2;
            CP16(d, s1);
            CP16(d + (BLO_OFF - BHI_OFF), s2);
        }
    };

    wmma::fragment<wmma::accumulator, 16, 16, 16, float> acc[4][4];
    #pragma unroll
    for (int mi = 0; mi < 4; mi++)
        #pragma unroll
        for (int ni = 0; ni < 4; ni++)
            wmma::fill_fragment(acc[mi][ni], 0.0f);

    issue(0); CP_COMMIT();
    if (NC > 1) issue(1);
    CP_COMMIT();

    for (int kb = 0; kb < NC; kb++) {
        CP_WAIT(1);
        __syncthreads();

        if (kb + STAGES - 1 < NC) issue(kb + STAGES - 1);
        CP_COMMIT();

        const char* base = sm + (kb % STAGES) * STAGE_BYTES;
        const bf16* Ahi = (const bf16*)(base + AHI_OFF);
        const bf16* Alo = (const bf16*)(base + ALO_OFF);
        const bf16* Bhi = (const bf16*)(base + BHI_OFF);
        const bf16* Blo = (const bf16*)(base + BLO_OFF);

        #pragma unroll
        for (int kk = 0; kk < 2; kk++) {
            wmma::fragment<wmma::matrix_b, 16, 16, 16, bf16, wmma::row_major> bfr[4];
            // ---- pass 1: A_hi x B_hi ----
            #pragma unroll
            for (int ni = 0; ni < 4; ni++)
                wmma::load_matrix_sync(bfr[ni], Bhi + (kk * 16) * LDB + warp_n * 64 + ni * 16, LDB);
            #pragma unroll
            for (int mi = 0; mi < 4; mi++) {
                wmma::fragment<wmma::matrix_a, 16, 16, 16, bf16, wmma::row_major> a;
                wmma::load_matrix_sync(a, Ahi + (warp_m * 64 + mi * 16) * LDA + kk * 16, LDA);
                #pragma unroll
                for (int ni = 0; ni < 4; ni++)
                    wmma::mma_sync(acc[mi][ni], a, bfr[ni], acc[mi][ni]);
            }
            // ---- pass 2: A_lo x B_hi (B frags reused) ----
            #pragma unroll
            for (int mi = 0; mi < 4; mi++) {
                wmma::fragment<wmma::matrix_a, 16, 16, 16, bf16, wmma::row_major> a;
                wmma::load_matrix_sync(a, Alo + (warp_m * 64 + mi * 16) * LDA + kk * 16, LDA);
                #pragma unroll
                for (int ni = 0; ni < 4; ni++)
                    wmma::mma_sync(acc[mi][ni], a, bfr[ni], acc[mi][ni]);
            }
            // ---- pass 3: A_hi x B_lo ----
            #pragma unroll
            for (int ni = 0; ni < 4; ni++)
                wmma::load_matrix_sync(bfr[ni], Blo + (kk * 16) * LDB + warp_n * 64 + ni * 16, LDB);
            #pragma unroll
            for (int mi = 0; mi < 4; mi++) {
                wmma::fragment<wmma::matrix_a, 16, 16, 16, bf16, wmma::row_major> a;
                wmma::load_matrix_sync(a, Ahi + (warp_m * 64 + mi * 16) * LDA + kk * 16, LDA);
                #pragma unroll
                for (int ni = 0; ni < 4; ni++)
                    wmma::mma_sync(acc[mi][ni], a, bfr[ni], acc[mi][ni]);
            }
        }
    }
    __syncthreads();

    // ---------------- epilogue via smem staging (128x256 fp32) ----------------
    float* Cs = (float*)sm;
    #pragma unroll
    for (int mi = 0; mi < 4; mi++)
        #pragma unroll
        for (int ni = 0; ni < 4; ni++)
            wmma::store_matrix_sync(Cs + (warp_m * 64 + mi * 16) * 256 + warp_n * 64 + ni * 16,
                                    acc[mi][ni], 256, wmma::mem_row_major);
    __syncthreads();

    #pragma unroll
    for (int i = 0; i < 32; i++) {
        const int f = tid + i * 256;          // 8192 float4 slots
        const int row = f >> 6, c4 = f & 63;
        const int grow = bm + row;
        const int gcol = bn + c4 * 4;
        float4 v = *(float4*)(Cs + row * 256 + c4 * 4);

        if (EPI == EPI_T || EPI == EPI_R1) {
            const size_t idx = (size_t)grow * Hn + gcol;
            float4 bv = *(const float4*)(bias + gcol);
            v.x += bv.x; v.y += bv.y; v.z += bv.z; v.w += bv.w;
            if (EPI == EPI_R1) { v.x=tanhf(v.x); v.y=tanhf(v.y); v.z=tanhf(v.z); v.w=tanhf(v.w); }
            store_planes(Ch, Cl, idx, v);
        } else if (EPI == EPI_M) {
            const size_t idx = (size_t)grow * Hn + gcol;
            v.x=tanhf(v.x); v.y=tanhf(v.y); v.z=tanhf(v.z); v.w=tanhf(v.w);
            store_planes(Ch, Cl, idx, v);
        } else if (EPI == EPI_ZR) {
            if (gcol < 256) {
                const size_t idx = (size_t)grow * Hn + gcol;
                float4 jv = *(const float4*)(jc + idx);
                v.x=sigf(v.x+jv.x); v.y=sigf(v.y+jv.y); v.z=sigf(v.z+jv.z); v.w=sigf(v.w+jv.w);
                *(float4*)(Cf + idx) = v;
            } else {
                const size_t idx = (size_t)grow * Hn + (gcol - 256);
                float4 jv = *(const float4*)(jc2 + idx);
                float4 hv = *(const float4*)(Hb + idx);
                v.x=sigf(v.x+jv.x)*hv.x; v.y=sigf(v.y+jv.y)*hv.y;
                v.z=sigf(v.z+jv.z)*hv.z; v.w=sigf(v.w+jv.w)*hv.w;
                store_planes(Ch, Cl, idx, v);
            }
        } else if (EPI == EPI_GRU) {
            const size_t idx = (size_t)grow * Hn + gcol;
            float4 jv = *(const float4*)(jc + idx);
            float4 hv = *(const float4*)(Hb + idx);
            float4 zv = *(const float4*)(Zb + idx);
            float t0=tanhf(v.x+jv.x), t1=tanhf(v.y+jv.y), t2=tanhf(v.z+jv.z), t3=tanhf(v.w+jv.w);
            v.x = hv.x + zv.x*(t0-hv.x); v.y = hv.y + zv.y*(t1-hv.y);
            v.z = hv.z + zv.z*(t2-hv.z); v.w = hv.w + zv.w*(t3-hv.w);
            *(float4*)(Cf + idx) = v;
            store_planes(Ch, Cl, idx, v);
        } else if (EPI == EPI_R2) {
            const size_t idx = (size_t)grow * Hn + gcol;
            float4 bv = *(const float4*)(bias + gcol);
            v.x += bv.x; v.y += bv.y; v.z += bv.z; v.w += bv.w;
            *(float4*)(Cf + idx) = v;
        }
    }
}

// ---------------- split / build kernels ----------------
__global__ void split_plain(const float* __restrict__ src, int n4, bf16* __restrict__ hi, bf16* __restrict__ lo)
{
    const int i = blockIdx.x * 256 + threadIdx.x;
    if (i < n4) {
        float4 v = *(const float4*)(src + i * 4);
        store_planes(hi, lo, (size_t)i * 4, v);
    }
}

__global__ void build_zrB(const float* __restrict__ Wz, const float* __restrict__ Wr,
                          const float* __restrict__ Uz, const float* __restrict__ Ur,
                          bf16* __restrict__ hi, bf16* __restrict__ lo)
{
    const int i = blockIdx.x * 256 + threadIdx.x;
    const int k = i >> 9, c = i & 511;
    float v;
    if (k < 256) v = (c < 256) ? Wz[k * Hn + c] : Wr[k * Hn + (c - 256)];
    else         v = (c < 256) ? Uz[(k - 256) * Hn + c] : Ur[(k - 256) * Hn + (c - 256)];
    bf16 h, l; split1(v, h, l);
    hi[i] = h; lo[i] = l;
}

__global__ void build_hB(const float* __restrict__ Wh, const float* __restrict__ Uh,
                         bf16* __restrict__ hi, bf16* __restrict__ lo)
{
    const int i = blockIdx.x * 256 + threadIdx.x;
    const int k = i >> 8, c = i & 255;
    float v = (k < 256) ? Wh[k * Hn + c] : Uh[(k - 256) * Hn + c];
    bf16 h, l; split1(v, h, l);
    hi[i] = h; lo[i] = l;
}

// ---------------- small kernels ----------------
__global__ void emb_kernel(const float* __restrict__ jets, const float* __restrict__ W_emb,
                           const float* __restrict__ b_emb, float* __restrict__ h,
                           bf16* __restrict__ hPh, bf16* __restrict__ hPl)
{
    const int row = blockIdx.x, j = threadIdx.x;
    __shared__ float sj[Fn];
    if (j < Fn) sj[j] = jets[(size_t)row * Fn + j];
    __syncthreads();
    float acc = b_emb[j];
    #pragma unroll
    for (int k = 0; k < Fn; k++) acc = fmaf(sj[k], W_emb[k * Hn + j], acc);
    const float v = tanhf(acc);
    const size_t idx = (size_t)row * Hn + j;
    h[idx] = v;
    bf16 hi, lo; split1(v, hi, lo);
    hPh[idx] = hi; hPl[idx] = lo;
}

__global__ void jc_kernel(const float* __restrict__ jets,
                          const float* __restrict__ Wz, const float* __restrict__ Wr,
                          const float* __restrict__ Wh,
                          const float* __restrict__ bz, const float* __restrict__ br,
                          const float* __restrict__ bh,
                          float* jcz, float* jcr, float* jch)
{
    const int row = blockIdx.x, j = threadIdx.x;
    __shared__ float sj[Fn];
    if (j < Fn) sj[j] = jets[(size_t)row * Fn + j];
    __syncthreads();
    float az = bz[j], ar = br[j], ah = bh[j];
    #pragma unroll
    for (int k = 0; k < Fn; k++) {
        const float s = sj[k];
        const int widx = (Hn + k) * Hn + j;
        az = fmaf(s, Wz[widx], az);
        ar = fmaf(s, Wr[widx], ar);
        ah = fmaf(s, Wh[widx], ah);
    }
    const size_t idx = (size_t)row * Hn + j;
    jcz[idx] = az; jcr[idx] = ar; jch[idx] = ah;
}

__global__ void reduce_kernel(const float* __restrict__ t2, float* __restrict__ out)
{
    const int idx = blockIdx.x * blockDim.x + threadIdx.x;
    const int b = idx >> 8, j = idx & 255;
    const float* p = t2 + (size_t)b * (Nn * Hn) + j;
    float acc = 0.0f;
    for (int n = 0; n < Nn; n++) acc += p[(size_t)n * Hn];
    out[idx] = acc;
}

// ---------------- launch ----------------
extern "C" void kernel_launch(void* const* d_in, const int* in_sizes, int n_in,
                              void* d_out, int out_size)
{
    const float* jets  = (const float*)d_in[0];
    const float* dads  = (const float*)d_in[1];
    const float* W_emb = (const float*)d_in[2];
    const float* b_emb = (const float*)d_in[3];
    const float* W_msg = (const float*)d_in[4];
    const float* b_msg = (const float*)d_in[5];
    const float* Wz    = (const float*)d_in[6];
    const float* Uz    = (const float*)d_in[7];
    const float* bz    = (const float*)d_in[8];
    const float* Wr    = (const float*)d_in[9];
    const float* Ur    = (const float*)d_in[10];
    const float* br    = (const float*)d_in[11];
    const float* Wh    = (const float*)d_in[12];
    const float* Uh    = (const float*)d_in[13];
    const float* bh    = (const float*)d_in[14];
    const float* W_r1  = (const float*)d_in[15];
    const float* b_r1  = (const float*)d_in[16];
    const float* W_r2  = (const float*)d_in[17];
    const float* b_r2  = (const float*)d_in[18];
    float* out = (float*)d_out;

    float *h, *z, *jcz, *jcr, *jch, *t2;
    bf16 *hP, *tP, *mP, *rhP, *daP, *wH, *wL;
    cudaGetSymbolAddress((void**)&h,   g_h);
    cudaGetSymbolAddress((void**)&z,   g_z);
    cudaGetSymbolAddress((void**)&jcz, g_jcz);
    cudaGetSymbolAddress((void**)&jcr, g_jcr);
    cudaGetSymbolAddress((void**)&jch, g_jch);
    cudaGetSymbolAddress((void**)&t2,  g_t2);
    cudaGetSymbolAddress((void**)&hP,  g_hP);
    cudaGetSymbolAddress((void**)&tP,  g_tP);
    cudaGetSymbolAddress((void**)&mP,  g_mP);
    cudaGetSymbolAddress((void**)&rhP, g_rhP);
    cudaGetSymbolAddress((void**)&daP, g_daP);
    cudaGetSymbolAddress((void**)&wH,  g_wH);
    cudaGetSymbolAddress((void**)&wL,  g_wL);

    bf16 *hPh = hP, *hPl = hP + PLANE;
    bf16 *tPh = tP, *tPl = tP + PLANE;
    bf16 *mPh = mP, *mPl = mP + PLANE;
    bf16 *rhPh = rhP, *rhPl = rhP + PLANE;
    bf16 *daPh = daP, *daPl = daP + PLANE;

    static bool attr_done = false;
    if (!attr_done) {
        cudaFuncSetAttribute(tc_gemm<EPI_T>,   cudaFuncAttributeMaxDynamicSharedMemorySize, SMEM_BYTES);
        cudaFuncSetAttribute(tc_gemm<EPI_M>,   cudaFuncAttributeMaxDynamicSharedMemorySize, SMEM_BYTES);
        cudaFuncSetAttribute(tc_gemm<EPI_ZR>,  cudaFuncAttributeMaxDynamicSharedMemorySize, SMEM_BYTES);
        cudaFuncSetAttribute(tc_gemm<EPI_GRU>, cudaFuncAttributeMaxDynamicSharedMemorySize, SMEM_BYTES);
        cudaFuncSetAttribute(tc_gemm<EPI_R1>,  cudaFuncAttributeMaxDynamicSharedMemorySize, SMEM_BYTES);
        cudaFuncSetAttribute(tc_gemm<EPI_R2>,  cudaFuncAttributeMaxDynamicSharedMemorySize, SMEM_BYTES);
        attr_done = true;
    }

    split_plain<<<PLANE/4/256, 256>>>(dads, PLANE/4, daPh, daPl);
    split_plain<<<65536/4/256, 256>>>(W_msg, 65536/4, wH + WOFF_MSG, wL + WOFF_MSG);
    split_plain<<<65536/4/256, 256>>>(W_r1,  65536/4, wH + WOFF_R1,  wL + WOFF_R1);
    split_plain<<<65536/4/256, 256>>>(W_r2,  65536/4, wH + WOFF_R2,  wL + WOFF_R2);
    build_zrB<<<262144/256, 256>>>(Wz, Wr, Uz, Ur, wH + WOFF_ZR, wL + WOFF_ZR);
    build_hB<<<131072/256, 256>>>(Wh, Uh, wH + WOFF_HB, wL + WOFF_HB);

    emb_kernel<<<ROWS, Hn>>>(jets, W_emb, b_emb, h, hPh, hPl);
    jc_kernel<<<ROWS, Hn>>>(jets, Wz, Wr, Wh, bz, br, bh, jcz, jcr, jch);

    dim3 grid1(1, ROWS/128);   // N=256 GEMMs: 128 CTAs
    dim3 grid2(2, ROWS/128);   // N=512 ZR: 256 CTAs
    for (int it = 0; it < N_ITERS; it++) {
        tc_gemm<EPI_T><<<grid1, 256, SMEM_BYTES>>>(
            hPh, hPl, nullptr, nullptr, wH + WOFF_MSG, wL + WOFF_MSG,
            256, 256, 0, b_msg, nullptr, nullptr, nullptr, nullptr,
            nullptr, tPh, tPl);
        tc_gemm<EPI_M><<<grid1, 256, SMEM_BYTES>>>(
            daPh, daPl, nullptr, nullptr, tPh, tPl,
            256, 256, 1, nullptr, nullptr, nullptr, nullptr, nullptr,
            nullptr, mPh, mPl);
        tc_gemm<EPI_ZR><<<grid2, 256, SMEM_BYTES>>>(
            mPh, mPl, hPh, hPl, wH + WOFF_ZR, wL + WOFF_ZR,
            512, 512, 0, nullptr, jcz, jcr, h, nullptr,
            z, rhPh, rhPl);
        tc_gemm<EPI_GRU><<<grid1, 256, SMEM_BYTES>>>(
            mPh, mPl, rhPh, rhPl, wH + WOFF_HB, wL + WOFF_HB,
            256, 512, 0, nullptr, jch, nullptr, h, z,
            h, hPh, hPl);
    }

    tc_gemm<EPI_R1><<<grid1, 256, SMEM_BYTES>>>(
        hPh, hPl, nullptr, nullptr, wH + WOFF_R1, wL + WOFF_R1,
        256, 256, 0, b_r1, nullptr, nullptr, nullptr, nullptr,
        nullptr, tPh, tPl);
    tc_gemm<EPI_R2><<<grid1, 256, SMEM_BYTES>>>(
        tPh, tPl, nullptr, nullptr, wH + WOFF_R2, wL + WOFF_R2,
        256, 256, 0, b_r2, nullptr, nullptr, nullptr, nullptr,
        t2, nullptr, nullptr);
    reduce_kernel<<<Bn, 256>>>(t2, out);
}

// round 9
// speedup vs baseline: 1.2317x; 1.2317x over previous
#include <cuda_runtime.h>
#include <cuda_bf16.h>
#include <cstdint>
#include <math.h>

typedef __nv_bfloat16 bf16;

// ---------------- problem dims ----------------
#define Bn 64
#define Nn 256
#define Fn 16
#define Hn 256
#define ROWS (Bn*Nn)          // 16384
#define N_ITERS 10
#define PLANE (ROWS*Hn)       // 4194304

// ---------------- scratch ----------------
__device__ float g_h  [PLANE];
__device__ float g_z  [PLANE];
__device__ float g_jcz[PLANE];
__device__ float g_jcr[PLANE];
__device__ float g_jch[PLANE];
__device__ float g_t2 [PLANE];
__device__ bf16 g_hP [2*PLANE];
__device__ bf16 g_tP [2*PLANE];
__device__ bf16 g_mP [2*PLANE];
__device__ bf16 g_rhP[2*PLANE];
__device__ bf16 g_daP[2*PLANE];
#define WOFF_MSG 0
#define WOFF_ZR  65536
#define WOFF_HB  327680
#define WOFF_R1  458752
#define WOFF_R2  524288
#define WTOTAL   589824
__device__ bf16 g_wH[WTOTAL];
__device__ bf16 g_wL[WTOTAL];

__device__ __forceinline__ float sigf(float x) { return 1.0f / (1.0f + expf(-x)); }

__device__ __forceinline__ uint32_t smem_u32(const void* p) {
    return (uint32_t)__cvta_generic_to_shared(p);
}
#define CP16(dst, src) asm volatile("cp.async.cg.shared.global [%0], [%1], 16;" :: "r"(dst), "l"(src))
#define CP_COMMIT()    asm volatile("cp.async.commit_group;" ::: "memory")
#define CP_WAIT(n)     asm volatile("cp.async.wait_group %0;" :: "n"(n) : "memory")

__device__ __forceinline__ void split1(float v, bf16& h, bf16& l) {
    h = __float2bfloat16(v);
    l = __float2bfloat16(v - __bfloat162float(h));
}
__device__ __forceinline__ void store_planes(bf16* Ph, bf16* Pl, size_t idx, float4 v) {
    __nv_bfloat162 h01 = __floats2bfloat162_rn(v.x, v.y);
    __nv_bfloat162 h23 = __floats2bfloat162_rn(v.z, v.w);
    float r0 = v.x - __low2float(h01), r1 = v.y - __high2float(h01);
    float r2 = v.z - __low2float(h23), r3 = v.w - __high2float(h23);
    __nv_bfloat162 l01 = __floats2bfloat162_rn(r0, r1);
    __nv_bfloat162 l23 = __floats2bfloat162_rn(r2, r3);
    uint2 hv, lv;
    hv.x = *(uint32_t*)&h01; hv.y = *(uint32_t*)&h23;
    lv.x = *(uint32_t*)&l01; lv.y = *(uint32_t*)&l23;
    *(uint2*)(Ph + idx) = hv;
    *(uint2*)(Pl + idx) = lv;
}
__device__ __forceinline__ void store_planes2(bf16* Ph, bf16* Pl, size_t idx, float2 v) {
    __nv_bfloat162 h = __floats2bfloat162_rn(v.x, v.y);
    float r0 = v.x - __low2float(h), r1 = v.y - __high2float(h);
    __nv_bfloat162 l = __floats2bfloat162_rn(r0, r1);
    *(uint32_t*)(Ph + idx) = *(uint32_t*)&h;
    *(uint32_t*)(Pl + idx) = *(uint32_t*)&l;
}

// ---------------- raw mma helpers ----------------
__device__ __forceinline__ void ldsm4(uint32_t addr, uint32_t& r0, uint32_t& r1, uint32_t& r2, uint32_t& r3) {
    asm volatile("ldmatrix.sync.aligned.m8n8.x4.shared.b16 {%0,%1,%2,%3}, [%4];"
                 : "=r"(r0), "=r"(r1), "=r"(r2), "=r"(r3) : "r"(addr));
}
__device__ __forceinline__ void ldsm4t(uint32_t addr, uint32_t& r0, uint32_t& r1, uint32_t& r2, uint32_t& r3) {
    asm volatile("ldmatrix.sync.aligned.m8n8.x4.trans.shared.b16 {%0,%1,%2,%3}, [%4];"
                 : "=r"(r0), "=r"(r1), "=r"(r2), "=r"(r3) : "r"(addr));
}
__device__ __forceinline__ void mma16816(float* d, const uint32_t* a, const uint32_t* b) {
    asm volatile("mma.sync.aligned.m16n8k16.row.col.f32.bf16.bf16.f32 "
                 "{%0,%1,%2,%3}, {%4,%5,%6,%7}, {%8,%9}, {%0,%1,%2,%3};"
                 : "+f"(d[0]), "+f"(d[1]), "+f"(d[2]), "+f"(d[3])
                 : "r"(a[0]), "r"(a[1]), "r"(a[2]), "r"(a[3]), "r"(b[0]), "r"(b[1]));
}

// ---------------- GEMM: 128x128 tile, raw mma, register-direct epilogue ------
enum { EPI_T = 0, EPI_M, EPI_ZR, EPI_GRU, EPI_R1, EPI_R2 };

#define STAGES 3
#define LDA 40
#define LDB 136
#define AHI_OFF 0
#define ALO_OFF 10240
#define BHI_OFF 20480
#define BLO_OFF 29184
#define STAGE_BYTES 37888
#define SMEM_BYTES (STAGES*STAGE_BYTES)   // 113664

template<int EPI>
__global__ void __launch_bounds__(256, 2)
tc_gemm(const bf16* __restrict__ A0h, const bf16* __restrict__ A0l,
        const bf16* __restrict__ A1h, const bf16* __restrict__ A1l,
        const bf16* __restrict__ Bh,  const bf16* __restrict__ Bl,
        int NB, int K, int batched,
        const float* __restrict__ bias,
        const float* __restrict__ jc,  const float* __restrict__ jc2,
        const float* __restrict__ Hb,  const float* __restrict__ Zb,
        float* Cf, bf16* Ch, bf16* Cl)
{
    extern __shared__ char sm[];
    const uint32_t smaddr = smem_u32(sm);

    const int tid = threadIdx.x, wid = tid >> 5, lane = tid & 31;
    const int bn = blockIdx.x * 128, bm = blockIdx.y * 128;
    const int warp_m = wid >> 2;        // 0..1
    const int warp_n = wid & 3;         // 0..3 (32 cols each)

    int am = bm;
    size_t aoff = 0, boff = 0;
    if (batched) {
        const int b = bm >> 8;
        aoff = (size_t)b * (Nn * Hn);
        boff = (size_t)b * (Nn * Hn);
        am = bm & (Nn - 1);
    }

    const int NC = K >> 5;

    auto issue = [&](int kb) {
        const int buf = kb % STAGES;
        const uint32_t sb = smaddr + buf * STAGE_BYTES;
        const int kk = (kb & 7) * 32;
        const bf16 *ah, *al; int arow;
        if (kb < 8) { ah = A0h + aoff; al = A0l + aoff; arow = am; }
        else        { ah = A1h;        al = A1l;        arow = bm; }
        #pragma unroll
        for (int i = 0; i < 2; i++) {
            const int c = tid + i * 256;
            {
                const int r = c >> 2, c8 = (c & 3) * 8;
                const bf16* s1 = ah + (size_t)(arow + r) * Hn + kk + c8;
                const bf16* s2 = al + (size_t)(arow + r) * Hn + kk + c8;
                const uint32_t d = sb + AHI_OFF + (uint32_t)(r * LDA + c8) * 2;
                CP16(d, s1);
                CP16(d + (ALO_OFF - AHI_OFF), s2);
            }
            {
                const int r = c >> 4, c8 = (c & 15) * 8;
                const bf16* s1 = Bh + boff + (size_t)(kb * 32 + r) * NB + bn + c8;
                const bf16* s2 = Bl + boff + (size_t)(kb * 32 + r) * NB + bn + c8;
                const uint32_t d = sb + BHI_OFF + (uint32_t)(r * LDB + c8) * 2;
                CP16(d, s1);
                CP16(d + (BLO_OFF - BHI_OFF), s2);
            }
        }
    };

    float acc[4][4][4];
    #pragma unroll
    for (int mi = 0; mi < 4; mi++)
        #pragma unroll
        for (int nj = 0; nj < 4; nj++)
            #pragma unroll
            for (int q = 0; q < 4; q++) acc[mi][nj][q] = 0.0f;

    // ldmatrix per-lane address components
    const uint32_t a_lrow = (uint32_t)(lane & 15);            // row within 16
    const uint32_t a_lcol = (uint32_t)((lane >> 4) << 3);     // 0 or 8 (k cols)
    const uint32_t b_lrow = (uint32_t)(lane & 15);            // k row within 16
    const uint32_t b_lcol = (uint32_t)((lane >> 4) << 3);     // 0 or 8 (n cols)

    issue(0); CP_COMMIT();
    if (NC > 1) issue(1);
    CP_COMMIT();

    for (int kb = 0; kb < NC; kb++) {
        CP_WAIT(1);
        __syncthreads();

        if (kb + STAGES - 1 < NC) issue(kb + STAGES - 1);
        CP_COMMIT();

        const uint32_t sb = smaddr + (kb % STAGES) * STAGE_BYTES;

        #pragma unroll
        for (int kk = 0; kk < 2; kk++) {
            // B base addresses for this kk (rows = k, cols = n)
            const uint32_t brow = (uint32_t)(kk * 16) + b_lrow;
            const uint32_t bcol0 = (uint32_t)(warp_n * 32) + b_lcol;
            uint32_t bfr[8];
            {   // B_hi: two x4.trans cover n-span 32
                const uint32_t ba = sb + BHI_OFF + (brow * LDB + bcol0) * 2;
                ldsm4t(ba,      bfr[0], bfr[1], bfr[2], bfr[3]);
                ldsm4t(ba + 32, bfr[4], bfr[5], bfr[6], bfr[7]);
            }
            const uint32_t arow0 = (uint32_t)(warp_m * 64) + a_lrow;
            const uint32_t acol = (uint32_t)(kk * 16) + a_lcol;
            // ---- pass 1: A_hi x B_hi ----
            #pragma unroll
            for (int mi = 0; mi < 4; mi++) {
                uint32_t a[4];
                ldsm4(sb + AHI_OFF + ((arow0 + mi * 16) * LDA + acol) * 2, a[0], a[1], a[2], a[3]);
                #pragma unroll
                for (int nj = 0; nj < 4; nj++) mma16816(acc[mi][nj], a, &bfr[nj * 2]);
            }
            // ---- pass 2: A_lo x B_hi (B frags reused) ----
            #pragma unroll
            for (int mi = 0; mi < 4; mi++) {
                uint32_t a[4];
                ldsm4(sb + ALO_OFF + ((arow0 + mi * 16) * LDA + acol) * 2, a[0], a[1], a[2], a[3]);
                #pragma unroll
                for (int nj = 0; nj < 4; nj++) mma16816(acc[mi][nj], a, &bfr[nj * 2]);
            }
            // ---- pass 3: A_hi x B_lo ----
            {
                const uint32_t ba = sb + BLO_OFF + (brow * LDB + bcol0) * 2;
                ldsm4t(ba,      bfr[0], bfr[1], bfr[2], bfr[3]);
                ldsm4t(ba + 32, bfr[4], bfr[5], bfr[6], bfr[7]);
            }
            #pragma unroll
            for (int mi = 0; mi < 4; mi++) {
                uint32_t a[4];
                ldsm4(sb + AHI_OFF + ((arow0 + mi * 16) * LDA + acol) * 2, a[0], a[1], a[2], a[3]);
                #pragma unroll
                for (int nj = 0; nj < 4; nj++) mma16816(acc[mi][nj], a, &bfr[nj * 2]);
            }
        }
    }

    // ---------------- register-direct epilogue ----------------
    const int r_in = lane >> 2;
    const int c_in = (lane & 3) * 2;

    #pragma unroll
    for (int mi = 0; mi < 4; mi++) {
        #pragma unroll
        for (int nj = 0; nj < 4; nj++) {
            #pragma unroll
            for (int half = 0; half < 2; half++) {
                const int row = bm + warp_m * 64 + mi * 16 + r_in + half * 8;
                const int col = bn + warp_n * 32 + nj * 8 + c_in;
                float2 v = make_float2(acc[mi][nj][half * 2], acc[mi][nj][half * 2 + 1]);

                if (EPI == EPI_T || EPI == EPI_R1) {
                    const size_t idx = (size_t)row * Hn + col;
                    float2 bv = *(const float2*)(bias + col);
                    v.x += bv.x; v.y += bv.y;
                    if (EPI == EPI_R1) { v.x = tanhf(v.x); v.y = tanhf(v.y); }
                    store_planes2(Ch, Cl, idx, v);
                } else if (EPI == EPI_M) {
                    const size_t idx = (size_t)row * Hn + col;
                    v.x = tanhf(v.x); v.y = tanhf(v.y);
                    store_planes2(Ch, Cl, idx, v);
                } else if (EPI == EPI_ZR) {
                    if (col < 256) {
                        const size_t idx = (size_t)row * Hn + col;
                        float2 jv = *(const float2*)(jc + idx);
                        v.x = sigf(v.x + jv.x); v.y = sigf(v.y + jv.y);
                        *(float2*)(Cf + idx) = v;
                    } else {
                        const size_t idx = (size_t)row * Hn + (col - 256);
                        float2 jv = *(const float2*)(jc2 + idx);
                        float2 hv = *(const float2*)(Hb + idx);
                        v.x = sigf(v.x + jv.x) * hv.x;
                        v.y = sigf(v.y + jv.y) * hv.y;
                        store_planes2(Ch, Cl, idx, v);
                    }
                } else if (EPI == EPI_GRU) {
                    const size_t idx = (size_t)row * Hn + col;
                    float2 jv = *(const float2*)(jc + idx);
                    float2 hv = *(const float2*)(Hb + idx);
                    float2 zv = *(const float2*)(Zb + idx);
                    float t0 = tanhf(v.x + jv.x), t1 = tanhf(v.y + jv.y);
                    v.x = hv.x + zv.x * (t0 - hv.x);
                    v.y = hv.y + zv.y * (t1 - hv.y);
                    *(float2*)(Cf + idx) = v;
                    store_planes2(Ch, Cl, idx, v);
                } else if (EPI == EPI_R2) {
                    const size_t idx = (size_t)row * Hn + col;
                    float2 bv = *(const float2*)(bias + col);
                    v.x += bv.x; v.y += bv.y;
                    *(float2*)(Cf + idx) = v;
                }
            }
        }
    }
}

// ---------------- split / build kernels ----------------
__global__ void split_plain(const float* __restrict__ src, int n4, bf16* __restrict__ hi, bf16* __restrict__ lo)
{
    const int i = blockIdx.x * 256 + threadIdx.x;
    if (i < n4) {
        float4 v = *(const float4*)(src + i * 4);
        store_planes(hi, lo, (size_t)i * 4, v);
    }
}

__global__ void build_zrB(const float* __restrict__ Wz, const float* __restrict__ Wr,
                          const float* __restrict__ Uz, const float* __restrict__ Ur,
                          bf16* __restrict__ hi, bf16* __restrict__ lo)
{
    const int i = blockIdx.x * 256 + threadIdx.x;
    const int k = i >> 9, c = i & 511;
    float v;
    if (k < 256) v = (c < 256) ? Wz[k * Hn + c] : Wr[k * Hn + (c - 256)];
    else         v = (c < 256) ? Uz[(k - 256) * Hn + c] : Ur[(k - 256) * Hn + (c - 256)];
    bf16 h, l; split1(v, h, l);
    hi[i] = h; lo[i] = l;
}

__global__ void build_hB(const float* __restrict__ Wh, const float* __restrict__ Uh,
                         bf16* __restrict__ hi, bf16* __restrict__ lo)
{
    const int i = blockIdx.x * 256 + threadIdx.x;
    const int k = i >> 8, c = i & 255;
    float v = (k < 256) ? Wh[k * Hn + c] : Uh[(k - 256) * Hn + c];
    bf16 h, l; split1(v, h, l);
    hi[i] = h; lo[i] = l;
}

// ---------------- small kernels ----------------
__global__ void emb_kernel(const float* __restrict__ jets, const float* __restrict__ W_emb,
                           const float* __restrict__ b_emb, float* __restrict__ h,
                           bf16* __restrict__ hPh, bf16* __restrict__ hPl)
{
    const int row = blockIdx.x, j = threadIdx.x;
    __shared__ float sj[Fn];
    if (j < Fn) sj[j] = jets[(size_t)row * Fn + j];
    __syncthreads();
    float acc = b_emb[j];
    #pragma unroll
    for (int k = 0; k < Fn; k++) acc = fmaf(sj[k], W_emb[k * Hn + j], acc);
    const float v = tanhf(acc);
    const size_t idx = (size_t)row * Hn + j;
    h[idx] = v;
    bf16 hi, lo; split1(v, hi, lo);
    hPh[idx] = hi; hPl[idx] = lo;
}

__global__ void jc_kernel(const float* __restrict__ jets,
                          const float* __restrict__ Wz, const float* __restrict__ Wr,
                          const float* __restrict__ Wh,
                          const float* __restrict__ bz, const float* __restrict__ br,
                          const float* __restrict__ bh,
                          float* jcz, float* jcr, float* jch)
{
    const int row = blockIdx.x, j = threadIdx.x;
    __shared__ float sj[Fn];
    if (j < Fn) sj[j] = jets[(size_t)row * Fn + j];
    __syncthreads();
    float az = bz[j], ar = br[j], ah = bh[j];
    #pragma unroll
    for (int k = 0; k < Fn; k++) {
        const float s = sj[k];
        const int widx = (Hn + k) * Hn + j;
        az = fmaf(s, Wz[widx], az);
        ar = fmaf(s, Wr[widx], ar);
        ah = fmaf(s, Wh[widx], ah);
    }
    const size_t idx = (size_t)row * Hn + j;
    jcz[idx] = az; jcr[idx] = ar; jch[idx] = ah;
}

__global__ void reduce_kernel(const float* __restrict__ t2, float* __restrict__ out)
{
    const int idx = blockIdx.x * blockDim.x + threadIdx.x;
    const int b = idx >> 8, j = idx & 255;
    const float* p = t2 + (size_t)b * (Nn * Hn) + j;
    float acc = 0.0f;
    for (int n = 0; n < Nn; n++) acc += p[(size_t)n * Hn];
    out[idx] = acc;
}

// ---------------- launch ----------------
extern "C" void kernel_launch(void* const* d_in, const int* in_sizes, int n_in,
                              void* d_out, int out_size)
{
    const float* jets  = (const float*)d_in[0];
    const float* dads  = (const float*)d_in[1];
    const float* W_emb = (const float*)d_in[2];
    const float* b_emb = (const float*)d_in[3];
    const float* W_msg = (const float*)d_in[4];
    const float* b_msg = (const float*)d_in[5];
    const float* Wz    = (const float*)d_in[6];
    const float* Uz    = (const float*)d_in[7];
    const float* bz    = (const float*)d_in[8];
    const float* Wr    = (const float*)d_in[9];
    const float* Ur    = (const float*)d_in[10];
    const float* br    = (const float*)d_in[11];
    const float* Wh    = (const float*)d_in[12];
    const float* Uh    = (const float*)d_in[13];
    const float* bh    = (const float*)d_in[14];
    const float* W_r1  = (const float*)d_in[15];
    const float* b_r1  = (const float*)d_in[16];
    const float* W_r2  = (const float*)d_in[17];
    const float* b_r2  = (const float*)d_in[18];
    float* out = (float*)d_out;

    float *h, *z, *jcz, *jcr, *jch, *t2;
    bf16 *hP, *tP, *mP, *rhP, *daP, *wH, *wL;
    cudaGetSymbolAddress((void**)&h,   g_h);
    cudaGetSymbolAddress((void**)&z,   g_z);
    cudaGetSymbolAddress((void**)&jcz, g_jcz);
    cudaGetSymbolAddress((void**)&jcr, g_jcr);
    cudaGetSymbolAddress((void**)&jch, g_jch);
    cudaGetSymbolAddress((void**)&t2,  g_t2);
    cudaGetSymbolAddress((void**)&hP,  g_hP);
    cudaGetSymbolAddress((void**)&tP,  g_tP);
    cudaGetSymbolAddress((void**)&mP,  g_mP);
    cudaGetSymbolAddress((void**)&rhP, g_rhP);
    cudaGetSymbolAddress((void**)&daP, g_daP);
    cudaGetSymbolAddress((void**)&wH,  g_wH);
    cudaGetSymbolAddress((void**)&wL,  g_wL);

    bf16 *hPh = hP, *hPl = hP + PLANE;
    bf16 *tPh = tP, *tPl = tP + PLANE;
    bf16 *mPh = mP, *mPl = mP + PLANE;
    bf16 *rhPh = rhP, *rhPl = rhP + PLANE;
    bf16 *daPh = daP, *daPl = daP + PLANE;

    static bool attr_done = false;
    if (!attr_done) {
        cudaFuncSetAttribute(tc_gemm<EPI_T>,   cudaFuncAttributeMaxDynamicSharedMemorySize, SMEM_BYTES);
        cudaFuncSetAttribute(tc_gemm<EPI_M>,   cudaFuncAttributeMaxDynamicSharedMemorySize, SMEM_BYTES);
        cudaFuncSetAttribute(tc_gemm<EPI_ZR>,  cudaFuncAttributeMaxDynamicSharedMemorySize, SMEM_BYTES);
        cudaFuncSetAttribute(tc_gemm<EPI_GRU>, cudaFuncAttributeMaxDynamicSharedMemorySize, SMEM_BYTES);
        cudaFuncSetAttribute(tc_gemm<EPI_R1>,  cudaFuncAttributeMaxDynamicSharedMemorySize, SMEM_BYTES);
        cudaFuncSetAttribute(tc_gemm<EPI_R2>,  cudaFuncAttributeMaxDynamicSharedMemorySize, SMEM_BYTES);
        attr_done = true;
    }

    split_plain<<<PLANE/4/256, 256>>>(dads, PLANE/4, daPh, daPl);
    split_plain<<<65536/4/256, 256>>>(W_msg, 65536/4, wH + WOFF_MSG, wL + WOFF_MSG);
    split_plain<<<65536/4/256, 256>>>(W_r1,  65536/4, wH + WOFF_R1,  wL + WOFF_R1);
    split_plain<<<65536/4/256, 256>>>(W_r2,  65536/4, wH + WOFF_R2,  wL + WOFF_R2);
    build_zrB<<<262144/256, 256>>>(Wz, Wr, Uz, Ur, wH + WOFF_ZR, wL + WOFF_ZR);
    build_hB<<<131072/256, 256>>>(Wh, Uh, wH + WOFF_HB, wL + WOFF_HB);

    emb_kernel<<<ROWS, Hn>>>(jets, W_emb, b_emb, h, hPh, hPl);
    jc_kernel<<<ROWS, Hn>>>(jets, Wz, Wr, Wh, bz, br, bh, jcz, jcr, jch);

    dim3 grid2(2, ROWS/128);
    dim3 grid4(4, ROWS/128);
    for (int it = 0; it < N_ITERS; it++) {
        tc_gemm<EPI_T><<<grid2, 256, SMEM_BYTES>>>(
            hPh, hPl, nullptr, nullptr, wH + WOFF_MSG, wL + WOFF_MSG,
            256, 256, 0, b_msg, nullptr, nullptr, nullptr, nullptr,
            nullptr, tPh, tPl);
        tc_gemm<EPI_M><<<grid2, 256, SMEM_BYTES>>>(
            daPh, daPl, nullptr, nullptr, tPh, tPl,
            256, 256, 1, nullptr, nullptr, nullptr, nullptr, nullptr,
            nullptr, mPh, mPl);
        tc_gemm<EPI_ZR><<<grid4, 256, SMEM_BYTES>>>(
            mPh, mPl, hPh, hPl, wH + WOFF_ZR, wL + WOFF_ZR,
            512, 512, 0, nullptr, jcz, jcr, h, nullptr,
            z, rhPh, rhPl);
        tc_gemm<EPI_GRU><<<grid2, 256, SMEM_BYTES>>>(
            mPh, mPl, rhPh, rhPl, wH + WOFF_HB, wL + WOFF_HB,
            256, 512, 0, nullptr, jch, nullptr, h, z,
            h, hPh, hPl);
    }

    tc_gemm<EPI_R1><<<grid2, 256, SMEM_BYTES>>>(
        hPh, hPl, nullptr, nullptr, wH + WOFF_R1, wL + WOFF_R1,
        256, 256, 0, b_r1, nullptr, nullptr, nullptr, nullptr,
        nullptr, tPh, tPl);
    tc_gemm<EPI_R2><<<grid2, 256, SMEM_BYTES>>>(
        tPh, tPl, nullptr, nullptr, wH + WOFF_R2, wL + WOFF_R2,
        256, 256, 0, b_r2, nullptr, nullptr, nullptr, nullptr,
        t2, nullptr, nullptr);
    reduce_kernel<<<Bn, 256>>>(t2, out);
}

// round 10
// speedup vs baseline: 1.4453x; 1.1734x over previous
#include <cuda_runtime.h>
#include <cuda_fp16.h>
#include <cstdint>
#include <math.h>

typedef __half f16;

// ---------------- problem dims ----------------
#define Bn 64
#define Nn 256
#define Fn 16
#define Hn 256
#define ROWS (Bn*Nn)          // 16384
#define N_ITERS 10
#define PLANE (ROWS*Hn)       // 4194304

// ---------------- scratch ----------------
__device__ float g_h  [PLANE];
__device__ float g_z  [PLANE];
__device__ float g_jcz[PLANE];
__device__ float g_jcr[PLANE];
__device__ float g_jch[PLANE];
__device__ float g_t2 [PLANE];
__device__ f16 g_hP [2*PLANE];
__device__ f16 g_tP [2*PLANE];
__device__ f16 g_mP [2*PLANE];
__device__ f16 g_rhP[2*PLANE];
__device__ f16 g_daP[2*PLANE];
#define WOFF_MSG 0
#define WOFF_ZR  65536
#define WOFF_HB  327680
#define WOFF_R1  458752
#define WOFF_R2  524288
#define WTOTAL   589824
__device__ f16 g_wH[WTOTAL];
__device__ f16 g_wL[WTOTAL];     // kept for layout symmetry; unused by 2-pass B

__device__ __forceinline__ float sigf(float x) { return 1.0f / (1.0f + expf(-x)); }

__device__ __forceinline__ uint32_t smem_u32(const void* p) {
    return (uint32_t)__cvta_generic_to_shared(p);
}
#define CP16(dst, src) asm volatile("cp.async.cg.shared.global [%0], [%1], 16;" :: "r"(dst), "l"(src))
#define CP_COMMIT()    asm volatile("cp.async.commit_group;" ::: "memory")
#define CP_WAIT(n)     asm volatile("cp.async.wait_group %0;" :: "n"(n) : "memory")

__device__ __forceinline__ void split1(float v, f16& h, f16& l) {
    h = __float2half_rn(v);
    l = __float2half_rn(v - __half2float(h));
}
__device__ __forceinline__ void store_planes(f16* Ph, f16* Pl, size_t idx, float4 v) {
    __half2 h01 = __floats2half2_rn(v.x, v.y);
    __half2 h23 = __floats2half2_rn(v.z, v.w);
    float r0 = v.x - __low2float(h01), r1 = v.y - __high2float(h01);
    float r2 = v.z - __low2float(h23), r3 = v.w - __high2float(h23);
    __half2 l01 = __floats2half2_rn(r0, r1);
    __half2 l23 = __floats2half2_rn(r2, r3);
    uint2 hv, lv;
    hv.x = *(uint32_t*)&h01; hv.y = *(uint32_t*)&h23;
    lv.x = *(uint32_t*)&l01; lv.y = *(uint32_t*)&l23;
    *(uint2*)(Ph + idx) = hv;
    *(uint2*)(Pl + idx) = lv;
}
__device__ __forceinline__ void store_planes2(f16* Ph, f16* Pl, size_t idx, float2 v) {
    __half2 h = __floats2half2_rn(v.x, v.y);
    float r0 = v.x - __low2float(h), r1 = v.y - __high2float(h);
    __half2 l = __floats2half2_rn(r0, r1);
    *(uint32_t*)(Ph + idx) = *(uint32_t*)&h;
    *(uint32_t*)(Pl + idx) = *(uint32_t*)&l;
}

// ---------------- raw mma helpers ----------------
__device__ __forceinline__ void ldsm4(uint32_t addr, uint32_t& r0, uint32_t& r1, uint32_t& r2, uint32_t& r3) {
    asm volatile("ldmatrix.sync.aligned.m8n8.x4.shared.b16 {%0,%1,%2,%3}, [%4];"
                 : "=r"(r0), "=r"(r1), "=r"(r2), "=r"(r3) : "r"(addr));
}
__device__ __forceinline__ void ldsm4t(uint32_t addr, uint32_t& r0, uint32_t& r1, uint32_t& r2, uint32_t& r3) {
    asm volatile("ldmatrix.sync.aligned.m8n8.x4.trans.shared.b16 {%0,%1,%2,%3}, [%4];"
                 : "=r"(r0), "=r"(r1), "=r"(r2), "=r"(r3) : "r"(addr));
}
__device__ __forceinline__ void mma16816(float* d, const uint32_t* a, const uint32_t* b) {
    asm volatile("mma.sync.aligned.m16n8k16.row.col.f32.f16.f16.f32 "
                 "{%0,%1,%2,%3}, {%4,%5,%6,%7}, {%8,%9}, {%0,%1,%2,%3};"
                 : "+f"(d[0]), "+f"(d[1]), "+f"(d[2]), "+f"(d[3])
                 : "r"(a[0]), "r"(a[1]), "r"(a[2]), "r"(a[3]), "r"(b[0]), "r"(b[1]));
}

// ---------------- GEMM: 128x128 tile, raw mma, fp16 2/3-pass split ------
enum { EPI_T = 0, EPI_M, EPI_ZR, EPI_GRU, EPI_R1, EPI_R2 };

#define STAGES 3
#define LDA 40
#define LDB 136
#define AHI_OFF 0
#define ALO_OFF 10240
#define BHI_OFF 20480
#define BLO_OFF 29184
#define STAGE_BYTES 37888
#define SMEM_BYTES (STAGES*STAGE_BYTES)   // 113664

template<int EPI, int PASSES>
__global__ void __launch_bounds__(256, 2)
tc_gemm(const f16* __restrict__ A0h, const f16* __restrict__ A0l,
        const f16* __restrict__ A1h, const f16* __restrict__ A1l,
        const f16* __restrict__ Bh,  const f16* __restrict__ Bl,
        int NB, int K, int batched,
        const float* __restrict__ bias,
        const float* __restrict__ jc,  const float* __restrict__ jc2,
        const float* __restrict__ Hb,  const float* __restrict__ Zb,
        float* Cf, f16* Ch, f16* Cl)
{
    extern __shared__ char sm[];
    const uint32_t smaddr = smem_u32(sm);

    const int tid = threadIdx.x, wid = tid >> 5, lane = tid & 31;
    const int bn = blockIdx.x * 128, bm = blockIdx.y * 128;
    const int warp_m = wid >> 2;        // 0..1
    const int warp_n = wid & 3;         // 0..3 (32 cols each)

    int am = bm;
    size_t aoff = 0, boff = 0;
    if (batched) {
        const int b = bm >> 8;
        aoff = (size_t)b * (Nn * Hn);
        boff = (size_t)b * (Nn * Hn);
        am = bm & (Nn - 1);
    }

    const int NC = K >> 5;

    auto issue = [&](int kb) {
        const int buf = kb % STAGES;
        const uint32_t sb = smaddr + buf * STAGE_BYTES;
        const int kk = (kb & 7) * 32;
        const f16 *ah, *al; int arow;
        if (kb < 8) { ah = A0h + aoff; al = A0l + aoff; arow = am; }
        else        { ah = A1h;        al = A1l;        arow = bm; }
        #pragma unroll
        for (int i = 0; i < 2; i++) {
            const int c = tid + i * 256;
            {
                const int r = c >> 2, c8 = (c & 3) * 8;
                const f16* s1 = ah + (size_t)(arow + r) * Hn + kk + c8;
                const f16* s2 = al + (size_t)(arow + r) * Hn + kk + c8;
                const uint32_t d = sb + AHI_OFF + (uint32_t)(r * LDA + c8) * 2;
                CP16(d, s1);
                CP16(d + (ALO_OFF - AHI_OFF), s2);
            }
            {
                const int r = c >> 4, c8 = (c & 15) * 8;
                const f16* s1 = Bh + boff + (size_t)(kb * 32 + r) * NB + bn + c8;
                const uint32_t d = sb + BHI_OFF + (uint32_t)(r * LDB + c8) * 2;
                CP16(d, s1);
                if (PASSES == 3) {
                    const f16* s2 = Bl + boff + (size_t)(kb * 32 + r) * NB + bn + c8;
                    CP16(d + (BLO_OFF - BHI_OFF), s2);
                }
            }
        }
    };

    float acc[4][4][4];
    #pragma unroll
    for (int mi = 0; mi < 4; mi++)
        #pragma unroll
        for (int nj = 0; nj < 4; nj++)
            #pragma unroll
            for (int q = 0; q < 4; q++) acc[mi][nj][q] = 0.0f;

    const uint32_t a_lrow = (uint32_t)(lane & 15);
    const uint32_t a_lcol = (uint32_t)((lane >> 4) << 3);
    const uint32_t b_lrow = (uint32_t)(lane & 15);
    const uint32_t b_lcol = (uint32_t)((lane >> 4) << 3);

    issue(0); CP_COMMIT();
    if (NC > 1) issue(1);
    CP_COMMIT();

    for (int kb = 0; kb < NC; kb++) {
        CP_WAIT(1);
        __syncthreads();

        if (kb + STAGES - 1 < NC) issue(kb + STAGES - 1);
        CP_COMMIT();

        const uint32_t sb = smaddr + (kb % STAGES) * STAGE_BYTES;

        #pragma unroll
        for (int kk = 0; kk < 2; kk++) {
            const uint32_t brow = (uint32_t)(kk * 16) + b_lrow;
            const uint32_t bcol0 = (uint32_t)(warp_n * 32) + b_lcol;
            uint32_t bfr[8];
            {   // B_hi
                const uint32_t ba = sb + BHI_OFF + (brow * LDB + bcol0) * 2;
                ldsm4t(ba,      bfr[0], bfr[1], bfr[2], bfr[3]);
                ldsm4t(ba + 32, bfr[4], bfr[5], bfr[6], bfr[7]);
            }
            const uint32_t arow0 = (uint32_t)(warp_m * 64) + a_lrow;
            const uint32_t acol = (uint32_t)(kk * 16) + a_lcol;
            // ---- pass 1: A_hi x B_hi ----
            #pragma unroll
            for (int mi = 0; mi < 4; mi++) {
                uint32_t a[4];
                ldsm4(sb + AHI_OFF + ((arow0 + mi * 16) * LDA + acol) * 2, a[0], a[1], a[2], a[3]);
                #pragma unroll
                for (int nj = 0; nj < 4; nj++) mma16816(acc[mi][nj], a, &bfr[nj * 2]);
            }
            // ---- pass 2: A_lo x B_hi ----
            #pragma unroll
            for (int mi = 0; mi < 4; mi++) {
                uint32_t a[4];
                ldsm4(sb + ALO_OFF + ((arow0 + mi * 16) * LDA + acol) * 2, a[0], a[1], a[2], a[3]);
                #pragma unroll
                for (int nj = 0; nj < 4; nj++) mma16816(acc[mi][nj], a, &bfr[nj * 2]);
            }
            // ---- pass 3 (only PASSES==3): A_hi x B_lo ----
            if (PASSES == 3) {
                const uint32_t ba = sb + BLO_OFF + (brow * LDB + bcol0) * 2;
                ldsm4t(ba,      bfr[0], bfr[1], bfr[2], bfr[3]);
                ldsm4t(ba + 32, bfr[4], bfr[5], bfr[6], bfr[7]);
                #pragma unroll
                for (int mi = 0; mi < 4; mi++) {
                    uint32_t a[4];
                    ldsm4(sb + AHI_OFF + ((arow0 + mi * 16) * LDA + acol) * 2, a[0], a[1], a[2], a[3]);
                    #pragma unroll
                    for (int nj = 0; nj < 4; nj++) mma16816(acc[mi][nj], a, &bfr[nj * 2]);
                }
            }
        }
    }

    // ---------------- register-direct epilogue ----------------
    const int r_in = lane >> 2;
    const int c_in = (lane & 3) * 2;

    #pragma unroll
    for (int mi = 0; mi < 4; mi++) {
        #pragma unroll
        for (int nj = 0; nj < 4; nj++) {
            #pragma unroll
            for (int half = 0; half < 2; half++) {
                const int row = bm + warp_m * 64 + mi * 16 + r_in + half * 8;
                const int col = bn + warp_n * 32 + nj * 8 + c_in;
                float2 v = make_float2(acc[mi][nj][half * 2], acc[mi][nj][half * 2 + 1]);

                if (EPI == EPI_T || EPI == EPI_R1) {
                    const size_t idx = (size_t)row * Hn + col;
                    float2 bv = *(const float2*)(bias + col);
                    v.x += bv.x; v.y += bv.y;
                    if (EPI == EPI_R1) { v.x = tanhf(v.x); v.y = tanhf(v.y); }
                    store_planes2(Ch, Cl, idx, v);
                } else if (EPI == EPI_M) {
                    const size_t idx = (size_t)row * Hn + col;
                    v.x = tanhf(v.x); v.y = tanhf(v.y);
                    store_planes2(Ch, Cl, idx, v);
                } else if (EPI == EPI_ZR) {
                    if (col < 256) {
                        const size_t idx = (size_t)row * Hn + col;
                        float2 jv = *(const float2*)(jc + idx);
                        v.x = sigf(v.x + jv.x); v.y = sigf(v.y + jv.y);
                        *(float2*)(Cf + idx) = v;
                    } else {
                        const size_t idx = (size_t)row * Hn + (col - 256);
                        float2 jv = *(const float2*)(jc2 + idx);
                        float2 hv = *(const float2*)(Hb + idx);
                        v.x = sigf(v.x + jv.x) * hv.x;
                        v.y = sigf(v.y + jv.y) * hv.y;
                        store_planes2(Ch, Cl, idx, v);
                    }
                } else if (EPI == EPI_GRU) {
                    const size_t idx = (size_t)row * Hn + col;
                    float2 jv = *(const float2*)(jc + idx);
                    float2 hv = *(const float2*)(Hb + idx);
                    float2 zv = *(const float2*)(Zb + idx);
                    float t0 = tanhf(v.x + jv.x), t1 = tanhf(v.y + jv.y);
                    v.x = hv.x + zv.x * (t0 - hv.x);
                    v.y = hv.y + zv.y * (t1 - hv.y);
                    *(float2*)(Cf + idx) = v;
                    store_planes2(Ch, Cl, idx, v);
                } else if (EPI == EPI_R2) {
                    const size_t idx = (size_t)row * Hn + col;
                    float2 bv = *(const float2*)(bias + col);
                    v.x += bv.x; v.y += bv.y;
                    *(float2*)(Cf + idx) = v;
                }
            }
        }
    }
}

// ---------------- split / build kernels ----------------
__global__ void split_plain(const float* __restrict__ src, int n4, f16* __restrict__ hi, f16* __restrict__ lo)
{
    const int i = blockIdx.x * 256 + threadIdx.x;
    if (i < n4) {
        float4 v = *(const float4*)(src + i * 4);
        store_planes(hi, lo, (size_t)i * 4, v);
    }
}

__global__ void build_zrB(const float* __restrict__ Wz, const float* __restrict__ Wr,
                          const float* __restrict__ Uz, const float* __restrict__ Ur,
                          f16* __restrict__ hi, f16* __restrict__ lo)
{
    const int i = blockIdx.x * 256 + threadIdx.x;
    const int k = i >> 9, c = i & 511;
    float v;
    if (k < 256) v = (c < 256) ? Wz[k * Hn + c] : Wr[k * Hn + (c - 256)];
    else         v = (c < 256) ? Uz[(k - 256) * Hn + c] : Ur[(k - 256) * Hn + (c - 256)];
    f16 h, l; split1(v, h, l);
    hi[i] = h; lo[i] = l;
}

__global__ void build_hB(const float* __restrict__ Wh, const float* __restrict__ Uh,
                         f16* __restrict__ hi, f16* __restrict__ lo)
{
    const int i = blockIdx.x * 256 + threadIdx.x;
    const int k = i >> 8, c = i & 255;
    float v = (k < 256) ? Wh[k * Hn + c] : Uh[(k - 256) * Hn + c];
    f16 h, l; split1(v, h, l);
    hi[i] = h; lo[i] = l;
}

// ---------------- small kernels ----------------
__global__ void emb_kernel(const float* __restrict__ jets, const float* __restrict__ W_emb,
                           const float* __restrict__ b_emb, float* __restrict__ h,
                           f16* __restrict__ hPh, f16* __restrict__ hPl)
{
    const int row = blockIdx.x, j = threadIdx.x;
    __shared__ float sj[Fn];
    if (j < Fn) sj[j] = jets[(size_t)row * Fn + j];
    __syncthreads();
    float acc = b_emb[j];
    #pragma unroll
    for (int k = 0; k < Fn; k++) acc = fmaf(sj[k], W_emb[k * Hn + j], acc);
    const float v = tanhf(acc);
    const size_t idx = (size_t)row * Hn + j;
    h[idx] = v;
    f16 hi, lo; split1(v, hi, lo);
    hPh[idx] = hi; hPl[idx] = lo;
}

__global__ void jc_kernel(const float* __restrict__ jets,
                          const float* __restrict__ Wz, const float* __restrict__ Wr,
                          const float* __restrict__ Wh,
                          const float* __restrict__ bz, const float* __restrict__ br,
                          const float* __restrict__ bh,
                          float* jcz, float* jcr, float* jch)
{
    const int row = blockIdx.x, j = threadIdx.x;
    __shared__ float sj[Fn];
    if (j < Fn) sj[j] = jets[(size_t)row * Fn + j];
    __syncthreads();
    float az = bz[j], ar = br[j], ah = bh[j];
    #pragma unroll
    for (int k = 0; k < Fn; k++) {
        const float s = sj[k];
        const int widx = (Hn + k) * Hn + j;
        az = fmaf(s, Wz[widx], az);
        ar = fmaf(s, Wr[widx], ar);
        ah = fmaf(s, Wh[widx], ah);
    }
    const size_t idx = (size_t)row * Hn + j;
    jcz[idx] = az; jcr[idx] = ar; jch[idx] = ah;
}

__global__ void reduce_kernel(const float* __restrict__ t2, float* __restrict__ out)
{
    const int idx = blockIdx.x * blockDim.x + threadIdx.x;
    const int b = idx >> 8, j = idx & 255;
    const float* p = t2 + (size_t)b * (Nn * Hn) + j;
    float acc = 0.0f;
    for (int n = 0; n < Nn; n++) acc += p[(size_t)n * Hn];
    out[idx] = acc;
}

// ---------------- launch ----------------
extern "C" void kernel_launch(void* const* d_in, const int* in_sizes, int n_in,
                              void* d_out, int out_size)
{
    const float* jets  = (const float*)d_in[0];
    const float* dads  = (const float*)d_in[1];
    const float* W_emb = (const float*)d_in[2];
    const float* b_emb = (const float*)d_in[3];
    const float* W_msg = (const float*)d_in[4];
    const float* b_msg = (const float*)d_in[5];
    const float* Wz    = (const float*)d_in[6];
    const float* Uz    = (const float*)d_in[7];
    const float* bz    = (const float*)d_in[8];
    const float* Wr    = (const float*)d_in[9];
    const float* Ur    = (const float*)d_in[10];
    const float* br    = (const float*)d_in[11];
    const float* Wh    = (const float*)d_in[12];
    const float* Uh    = (const float*)d_in[13];
    const float* bh    = (const float*)d_in[14];
    const float* W_r1  = (const float*)d_in[15];
    const float* b_r1  = (const float*)d_in[16];
    const float* W_r2  = (const float*)d_in[17];
    const float* b_r2  = (const float*)d_in[18];
    float* out = (float*)d_out;

    float *h, *z, *jcz, *jcr, *jch, *t2;
    f16 *hP, *tP, *mP, *rhP, *daP, *wH, *wL;
    cudaGetSymbolAddress((void**)&h,   g_h);
    cudaGetSymbolAddress((void**)&z,   g_z);
    cudaGetSymbolAddress((void**)&jcz, g_jcz);
    cudaGetSymbolAddress((void**)&jcr, g_jcr);
    cudaGetSymbolAddress((void**)&jch, g_jch);
    cudaGetSymbolAddress((void**)&t2,  g_t2);
    cudaGetSymbolAddress((void**)&hP,  g_hP);
    cudaGetSymbolAddress((void**)&tP,  g_tP);
    cudaGetSymbolAddress((void**)&mP,  g_mP);
    cudaGetSymbolAddress((void**)&rhP, g_rhP);
    cudaGetSymbolAddress((void**)&daP, g_daP);
    cudaGetSymbolAddress((void**)&wH,  g_wH);
    cudaGetSymbolAddress((void**)&wL,  g_wL);

    f16 *hPh = hP, *hPl = hP + PLANE;
    f16 *tPh = tP, *tPl = tP + PLANE;
    f16 *mPh = mP, *mPl = mP + PLANE;
    f16 *rhPh = rhP, *rhPl = rhP + PLANE;
    f16 *daPh = daP, *daPl = daP + PLANE;

    static bool attr_done = false;
    if (!attr_done) {
        cudaFuncSetAttribute(tc_gemm<EPI_T,2>,   cudaFuncAttributeMaxDynamicSharedMemorySize, SMEM_BYTES);
        cudaFuncSetAttribute(tc_gemm<EPI_M,3>,   cudaFuncAttributeMaxDynamicSharedMemorySize, SMEM_BYTES);
        cudaFuncSetAttribute(tc_gemm<EPI_ZR,2>,  cudaFuncAttributeMaxDynamicSharedMemorySize, SMEM_BYTES);
        cudaFuncSetAttribute(tc_gemm<EPI_GRU,2>, cudaFuncAttributeMaxDynamicSharedMemorySize, SMEM_BYTES);
        cudaFuncSetAttribute(tc_gemm<EPI_R1,2>,  cudaFuncAttributeMaxDynamicSharedMemorySize, SMEM_BYTES);
        cudaFuncSetAttribute(tc_gemm<EPI_R2,2>,  cudaFuncAttributeMaxDynamicSharedMemorySize, SMEM_BYTES);
        attr_done = true;
    }

    split_plain<<<PLANE/4/256, 256>>>(dads, PLANE/4, daPh, daPl);
    split_plain<<<65536/4/256, 256>>>(W_msg, 65536/4, wH + WOFF_MSG, wL + WOFF_MSG);
    split_plain<<<65536/4/256, 256>>>(W_r1,  65536/4, wH + WOFF_R1,  wL + WOFF_R1);
    split_plain<<<65536/4/256, 256>>>(W_r2,  65536/4, wH + WOFF_R2,  wL + WOFF_R2);
    build_zrB<<<262144/256, 256>>>(Wz, Wr, Uz, Ur, wH + WOFF_ZR, wL + WOFF_ZR);
    build_hB<<<131072/256, 256>>>(Wh, Uh, wH + WOFF_HB, wL + WOFF_HB);

    emb_kernel<<<ROWS, Hn>>>(jets, W_emb, b_emb, h, hPh, hPl);
    jc_kernel<<<ROWS, Hn>>>(jets, Wz, Wr, Wh, bz, br, bh, jcz, jcr, jch);

    dim3 grid2(2, ROWS/128);
    dim3 grid4(4, ROWS/128);
    for (int it = 0; it < N_ITERS; it++) {
        // t = h @ W_msg + b_msg   (2-pass; t stored as hi+lo planes)
        tc_gemm<EPI_T,2><<<grid2, 256, SMEM_BYTES>>>(
            hPh, hPl, nullptr, nullptr, wH + WOFF_MSG, wL + WOFF_MSG,
            256, 256, 0, b_msg, nullptr, nullptr, nullptr, nullptr,
            nullptr, tPh, tPl);
        // m = tanh(dads @ t)   (3-pass: dads is non-negative, no sign cancellation)
        tc_gemm<EPI_M,3><<<grid2, 256, SMEM_BYTES>>>(
            daPh, daPl, nullptr, nullptr, tPh, tPl,
            256, 256, 1, nullptr, nullptr, nullptr, nullptr, nullptr,
            nullptr, mPh, mPl);
        // [z|r] gates (2-pass)
        tc_gemm<EPI_ZR,2><<<grid4, 256, SMEM_BYTES>>>(
            mPh, mPl, hPh, hPl, wH + WOFF_ZR, wL + WOFF_ZR,
            512, 512, 0, nullptr, jcz, jcr, h, nullptr,
            z, rhPh, rhPl);
        // GRU update (2-pass)
        tc_gemm<EPI_GRU,2><<<grid2, 256, SMEM_BYTES>>>(
            mPh, mPl, rhPh, rhPl, wH + WOFF_HB, wL + WOFF_HB,
            256, 512, 0, nullptr, jch, nullptr, h, z,
            h, hPh, hPl);
    }

    tc_gemm<EPI_R1,2><<<grid2, 256, SMEM_BYTES>>>(
        hPh, hPl, nullptr, nullptr, wH + WOFF_R1, wL + WOFF_R1,
        256, 256, 0, b_r1, nullptr, nullptr, nullptr, nullptr,
        nullptr, tPh, tPl);
    tc_gemm<EPI_R2,2><<<grid2, 256, SMEM_BYTES>>>(
        tPh, tPl, nullptr, nullptr, wH + WOFF_R2, wL + WOFF_R2,
        256, 256, 0, b_r2, nullptr, nullptr, nullptr, nullptr,
        t2, nullptr, nullptr);
    reduce_kernel<<<Bn, 256>>>(t2, out);
}

// round 11
// speedup vs baseline: 1.6878x; 1.1678x over previous
#include <cuda_runtime.h>
#include <cuda_fp16.h>
#include <cstdint>
#include <math.h>

typedef __half f16;

// ---------------- problem dims ----------------
#define Bn 64
#define Nn 256
#define Fn 16
#define Hn 256
#define ROWS (Bn*Nn)          // 16384
#define N_ITERS 10
#define PLANE (ROWS*Hn)       // 4194304

// ---------------- scratch ----------------
__device__ float g_h  [PLANE];
__device__ float g_z  [PLANE];
__device__ float g_jcz[PLANE];
__device__ float g_jcr[PLANE];
__device__ float g_jch[PLANE];
__device__ float g_t2 [PLANE];
__device__ f16 g_hP [2*PLANE];
__device__ f16 g_tP [2*PLANE];
__device__ f16 g_mP [2*PLANE];
__device__ f16 g_rhP[2*PLANE];
__device__ f16 g_daP[2*PLANE];
#define WOFF_MSG 0
#define WOFF_ZR  65536
#define WOFF_HB  327680
#define WOFF_R1  458752
#define WOFF_R2  524288
#define WTOTAL   589824
__device__ f16 g_wH[WTOTAL];
__device__ f16 g_wL[WTOTAL];

__device__ __forceinline__ float sigf(float x) { return 1.0f / (1.0f + expf(-x)); }

__device__ __forceinline__ uint32_t smem_u32(const void* p) {
    return (uint32_t)__cvta_generic_to_shared(p);
}
#define CP16(dst, src) asm volatile("cp.async.cg.shared.global [%0], [%1], 16;" :: "r"(dst), "l"(src))
#define CP_COMMIT()    asm volatile("cp.async.commit_group;" ::: "memory")
#define CP_WAIT(n)     asm volatile("cp.async.wait_group %0;" :: "n"(n) : "memory")

__device__ __forceinline__ void split1(float v, f16& h, f16& l) {
    h = __float2half_rn(v);
    l = __float2half_rn(v - __half2float(h));
}
__device__ __forceinline__ void store_planes(f16* Ph, f16* Pl, size_t idx, float4 v) {
    __half2 h01 = __floats2half2_rn(v.x, v.y);
    __half2 h23 = __floats2half2_rn(v.z, v.w);
    float r0 = v.x - __low2float(h01), r1 = v.y - __high2float(h01);
    float r2 = v.z - __low2float(h23), r3 = v.w - __high2float(h23);
    __half2 l01 = __floats2half2_rn(r0, r1);
    __half2 l23 = __floats2half2_rn(r2, r3);
    uint2 hv, lv;
    hv.x = *(uint32_t*)&h01; hv.y = *(uint32_t*)&h23;
    lv.x = *(uint32_t*)&l01; lv.y = *(uint32_t*)&l23;
    *(uint2*)(Ph + idx) = hv;
    *(uint2*)(Pl + idx) = lv;
}
__device__ __forceinline__ void store_planes2(f16* Ph, f16* Pl, size_t idx, float2 v) {
    __half2 h = __floats2half2_rn(v.x, v.y);
    float r0 = v.x - __low2float(h), r1 = v.y - __high2float(h);
    __half2 l = __floats2half2_rn(r0, r1);
    *(uint32_t*)(Ph + idx) = *(uint32_t*)&h;
    *(uint32_t*)(Pl + idx) = *(uint32_t*)&l;
}

// ---------------- raw mma helpers ----------------
__device__ __forceinline__ void ldsm4(uint32_t addr, uint32_t& r0, uint32_t& r1, uint32_t& r2, uint32_t& r3) {
    asm volatile("ldmatrix.sync.aligned.m8n8.x4.shared.b16 {%0,%1,%2,%3}, [%4];"
                 : "=r"(r0), "=r"(r1), "=r"(r2), "=r"(r3) : "r"(addr));
}
__device__ __forceinline__ void ldsm4t(uint32_t addr, uint32_t& r0, uint32_t& r1, uint32_t& r2, uint32_t& r3) {
    asm volatile("ldmatrix.sync.aligned.m8n8.x4.trans.shared.b16 {%0,%1,%2,%3}, [%4];"
                 : "=r"(r0), "=r"(r1), "=r"(r2), "=r"(r3) : "r"(addr));
}
__device__ __forceinline__ void mma16816(float* d, const uint32_t* a, const uint32_t* b) {
    asm volatile("mma.sync.aligned.m16n8k16.row.col.f32.f16.f16.f32 "
                 "{%0,%1,%2,%3}, {%4,%5,%6,%7}, {%8,%9}, {%0,%1,%2,%3};"
                 : "+f"(d[0]), "+f"(d[1]), "+f"(d[2]), "+f"(d[3])
                 : "r"(a[0]), "r"(a[1]), "r"(a[2]), "r"(a[3]), "r"(b[0]), "r"(b[1]));
}

// ---------------- GEMM: 128x128 tile, raw mma, fp16 1/2/3-pass split ------
enum { EPI_T = 0, EPI_M, EPI_Z, EPI_R, EPI_GRU, EPI_R1, EPI_R2 };

#define STAGES 3
#define LDA 40
#define LDB 136
#define AHI_OFF 0
#define ALO_OFF 10240
#define BHI_OFF 20480
#define BLO_OFF 29184
#define STAGE_BYTES 37888
#define SMEM_BYTES (STAGES*STAGE_BYTES)   // 113664

template<int EPI, int PASSES>
__global__ void __launch_bounds__(256, 2)
tc_gemm(const f16* __restrict__ A0h, const f16* __restrict__ A0l,
        const f16* __restrict__ A1h, const f16* __restrict__ A1l,
        const f16* __restrict__ Bh,  const f16* __restrict__ Bl,
        int NB, int K, int batched,
        const float* __restrict__ bias,
        const float* __restrict__ jc,
        const float* __restrict__ Hb,  const float* __restrict__ Zb,
        float* Cf, f16* Ch, f16* Cl)
{
    extern __shared__ char sm[];
    const uint32_t smaddr = smem_u32(sm);

    const int tid = threadIdx.x, wid = tid >> 5, lane = tid & 31;
    const int bn = blockIdx.x * 128, bm = blockIdx.y * 128;
    const int warp_m = wid >> 2;
    const int warp_n = wid & 3;

    int am = bm;
    size_t aoff = 0, boff = 0;
    if (batched) {
        const int b = bm >> 8;
        aoff = (size_t)b * (Nn * Hn);
        boff = (size_t)b * (Nn * Hn);
        am = bm & (Nn - 1);
    }

    const int NC = K >> 5;

    auto issue = [&](int kb) {
        const int buf = kb % STAGES;
        const uint32_t sb = smaddr + buf * STAGE_BYTES;
        const int kk = (kb & 7) * 32;
        const f16 *ah, *al; int arow;
        if (kb < 8) { ah = A0h + aoff; al = A0l + aoff; arow = am; }
        else        { ah = A1h;        al = A1l;        arow = bm; }
        #pragma unroll
        for (int i = 0; i < 2; i++) {
            const int c = tid + i * 256;
            {
                const int r = c >> 2, c8 = (c & 3) * 8;
                const f16* s1 = ah + (size_t)(arow + r) * Hn + kk + c8;
                const uint32_t d = sb + AHI_OFF + (uint32_t)(r * LDA + c8) * 2;
                CP16(d, s1);
                if (PASSES >= 2) {
                    const f16* s2 = al + (size_t)(arow + r) * Hn + kk + c8;
                    CP16(d + (ALO_OFF - AHI_OFF), s2);
                }
            }
            {
                const int r = c >> 4, c8 = (c & 15) * 8;
                const f16* s1 = Bh + boff + (size_t)(kb * 32 + r) * NB + bn + c8;
                const uint32_t d = sb + BHI_OFF + (uint32_t)(r * LDB + c8) * 2;
                CP16(d, s1);
                if (PASSES == 3) {
                    const f16* s2 = Bl + boff + (size_t)(kb * 32 + r) * NB + bn + c8;
                    CP16(d + (BLO_OFF - BHI_OFF), s2);
                }
            }
        }
    };

    float acc[4][4][4];
    #pragma unroll
    for (int mi = 0; mi < 4; mi++)
        #pragma unroll
        for (int nj = 0; nj < 4; nj++)
            #pragma unroll
            for (int q = 0; q < 4; q++) acc[mi][nj][q] = 0.0f;

    const uint32_t a_lrow = (uint32_t)(lane & 15);
    const uint32_t a_lcol = (uint32_t)((lane >> 4) << 3);
    const uint32_t b_lrow = (uint32_t)(lane & 15);
    const uint32_t b_lcol = (uint32_t)((lane >> 4) << 3);

    issue(0); CP_COMMIT();
    if (NC > 1) issue(1);
    CP_COMMIT();

    for (int kb = 0; kb < NC; kb++) {
        CP_WAIT(1);
        __syncthreads();

        if (kb + STAGES - 1 < NC) issue(kb + STAGES - 1);
        CP_COMMIT();

        const uint32_t sb = smaddr + (kb % STAGES) * STAGE_BYTES;

        #pragma unroll
        for (int kk = 0; kk < 2; kk++) {
            const uint32_t brow = (uint32_t)(kk * 16) + b_lrow;
            const uint32_t bcol0 = (uint32_t)(warp_n * 32) + b_lcol;
            uint32_t bfr[8];
            {   // B_hi
                const uint32_t ba = sb + BHI_OFF + (brow * LDB + bcol0) * 2;
                ldsm4t(ba,      bfr[0], bfr[1], bfr[2], bfr[3]);
                ldsm4t(ba + 32, bfr[4], bfr[5], bfr[6], bfr[7]);
            }
            const uint32_t arow0 = (uint32_t)(warp_m * 64) + a_lrow;
            const uint32_t acol = (uint32_t)(kk * 16) + a_lcol;
            // ---- pass 1: A_hi x B_hi ----
            #pragma unroll
            for (int mi = 0; mi < 4; mi++) {
                uint32_t a[4];
                ldsm4(sb + AHI_OFF + ((arow0 + mi * 16) * LDA + acol) * 2, a[0], a[1], a[2], a[3]);
                #pragma unroll
                for (int nj = 0; nj < 4; nj++) mma16816(acc[mi][nj], a, &bfr[nj * 2]);
            }
            // ---- pass 2: A_lo x B_hi ----
            if (PASSES >= 2) {
                #pragma unroll
                for (int mi = 0; mi < 4; mi++) {
                    uint32_t a[4];
                    ldsm4(sb + ALO_OFF + ((arow0 + mi * 16) * LDA + acol) * 2, a[0], a[1], a[2], a[3]);
                    #pragma unroll
                    for (int nj = 0; nj < 4; nj++) mma16816(acc[mi][nj], a, &bfr[nj * 2]);
                }
            }
            // ---- pass 3: A_hi x B_lo ----
            if (PASSES == 3) {
                const uint32_t ba = sb + BLO_OFF + (brow * LDB + bcol0) * 2;
                ldsm4t(ba,      bfr[0], bfr[1], bfr[2], bfr[3]);
                ldsm4t(ba + 32, bfr[4], bfr[5], bfr[6], bfr[7]);
                #pragma unroll
                for (int mi = 0; mi < 4; mi++) {
                    uint32_t a[4];
                    ldsm4(sb + AHI_OFF + ((arow0 + mi * 16) * LDA + acol) * 2, a[0], a[1], a[2], a[3]);
                    #pragma unroll
                    for (int nj = 0; nj < 4; nj++) mma16816(acc[mi][nj], a, &bfr[nj * 2]);
                }
            }
        }
    }

    // ---------------- register-direct epilogue ----------------
    const int r_in = lane >> 2;
    const int c_in = (lane & 3) * 2;

    #pragma unroll
    for (int mi = 0; mi < 4; mi++) {
        #pragma unroll
        for (int nj = 0; nj < 4; nj++) {
            #pragma unroll
            for (int half = 0; half < 2; half++) {
                const int row = bm + warp_m * 64 + mi * 16 + r_in + half * 8;
                const int col = bn + warp_n * 32 + nj * 8 + c_in;
                float2 v = make_float2(acc[mi][nj][half * 2], acc[mi][nj][half * 2 + 1]);
                const size_t idx = (size_t)row * Hn + col;

                if (EPI == EPI_T || EPI == EPI_R1) {
                    float2 bv = *(const float2*)(bias + col);
                    v.x += bv.x; v.y += bv.y;
                    if (EPI == EPI_R1) { v.x = tanhf(v.x); v.y = tanhf(v.y); }
                    store_planes2(Ch, Cl, idx, v);
                } else if (EPI == EPI_M) {
                    v.x = tanhf(v.x); v.y = tanhf(v.y);
                    store_planes2(Ch, Cl, idx, v);
                } else if (EPI == EPI_Z) {
                    float2 jv = *(const float2*)(jc + idx);
                    v.x = sigf(v.x + jv.x); v.y = sigf(v.y + jv.y);
                    *(float2*)(Cf + idx) = v;
                } else if (EPI == EPI_R) {
                    float2 jv = *(const float2*)(jc + idx);
                    float2 hv = *(const float2*)(Hb + idx);
                    v.x = sigf(v.x + jv.x) * hv.x;
                    v.y = sigf(v.y + jv.y) * hv.y;
                    store_planes2(Ch, Cl, idx, v);
                } else if (EPI == EPI_GRU) {
                    float2 jv = *(const float2*)(jc + idx);
                    float2 hv = *(const float2*)(Hb + idx);
                    float2 zv = *(const float2*)(Zb + idx);
                    float t0 = tanhf(v.x + jv.x), t1 = tanhf(v.y + jv.y);
                    v.x = hv.x + zv.x * (t0 - hv.x);
                    v.y = hv.y + zv.y * (t1 - hv.y);
                    *(float2*)(Cf + idx) = v;
                    store_planes2(Ch, Cl, idx, v);
                } else if (EPI == EPI_R2) {
                    float2 bv = *(const float2*)(bias + col);
                    v.x += bv.x; v.y += bv.y;
                    *(float2*)(Cf + idx) = v;
                }
            }
        }
    }
}

// ---------------- split / build kernels ----------------
__global__ void split_plain(const float* __restrict__ src, int n4, f16* __restrict__ hi, f16* __restrict__ lo)
{
    const int i = blockIdx.x * 256 + threadIdx.x;
    if (i < n4) {
        float4 v = *(const float4*)(src + i * 4);
        store_planes(hi, lo, (size_t)i * 4, v);
    }
}

__global__ void build_zrB(const float* __restrict__ Wz, const float* __restrict__ Wr,
                          const float* __restrict__ Uz, const float* __restrict__ Ur,
                          f16* __restrict__ hi, f16* __restrict__ lo)
{
    const int i = blockIdx.x * 256 + threadIdx.x;
    const int k = i >> 9, c = i & 511;
    float v;
    if (k < 256) v = (c < 256) ? Wz[k * Hn + c] : Wr[k * Hn + (c - 256)];
    else         v = (c < 256) ? Uz[(k - 256) * Hn + c] : Ur[(k - 256) * Hn + (c - 256)];
    f16 h, l; split1(v, h, l);
    hi[i] = h; lo[i] = l;
}

__global__ void build_hB(const float* __restrict__ Wh, const float* __restrict__ Uh,
                         f16* __restrict__ hi, f16* __restrict__ lo)
{
    const int i = blockIdx.x * 256 + threadIdx.x;
    const int k = i >> 8, c = i & 255;
    float v = (k < 256) ? Wh[k * Hn + c] : Uh[(k - 256) * Hn + c];
    f16 h, l; split1(v, h, l);
    hi[i] = h; lo[i] = l;
}

// ---------------- small kernels ----------------
__global__ void emb_kernel(const float* __restrict__ jets, const float* __restrict__ W_emb,
                           const float* __restrict__ b_emb, float* __restrict__ h,
                           f16* __restrict__ hPh, f16* __restrict__ hPl)
{
    const int row = blockIdx.x, j = threadIdx.x;
    __shared__ float sj[Fn];
    if (j < Fn) sj[j] = jets[(size_t)row * Fn + j];
    __syncthreads();
    float acc = b_emb[j];
    #pragma unroll
    for (int k = 0; k < Fn; k++) acc = fmaf(sj[k], W_emb[k * Hn + j], acc);
    const float v = tanhf(acc);
    const size_t idx = (size_t)row * Hn + j;
    h[idx] = v;
    f16 hi, lo; split1(v, hi, lo);
    hPh[idx] = hi; hPl[idx] = lo;
}

__global__ void jc_kernel(const float* __restrict__ jets,
                          const float* __restrict__ Wz, const float* __restrict__ Wr,
                          const float* __restrict__ Wh,
                          const float* __restrict__ bz, const float* __restrict__ br,
                          const float* __restrict__ bh,
                          float* jcz, float* jcr, float* jch)
{
    const int row = blockIdx.x, j = threadIdx.x;
    __shared__ float sj[Fn];
    if (j < Fn) sj[j] = jets[(size_t)row * Fn + j];
    __syncthreads();
    float az = bz[j], ar = br[j], ah = bh[j];
    #pragma unroll
    for (int k = 0; k < Fn; k++) {
        const float s = sj[k];
        const int widx = (Hn + k) * Hn + j;
        az = fmaf(s, Wz[widx], az);
        ar = fmaf(s, Wr[widx], ar);
        ah = fmaf(s, Wh[widx], ah);
    }
    const size_t idx = (size_t)row * Hn + j;
    jcz[idx] = az; jcr[idx] = ar; jch[idx] = ah;
}

__global__ void reduce_kernel(const float* __restrict__ t2, float* __restrict__ out)
{
    const int idx = blockIdx.x * blockDim.x + threadIdx.x;
    const int b = idx >> 8, j = idx & 255;
    const float* p = t2 + (size_t)b * (Nn * Hn) + j;
    float acc = 0.0f;
    for (int n = 0; n < Nn; n++) acc += p[(size_t)n * Hn];
    out[idx] = acc;
}

// ---------------- launch ----------------
extern "C" void kernel_launch(void* const* d_in, const int* in_sizes, int n_in,
                              void* d_out, int out_size)
{
    const float* jets  = (const float*)d_in[0];
    const float* dads  = (const float*)d_in[1];
    const float* W_emb = (const float*)d_in[2];
    const float* b_emb = (const float*)d_in[3];
    const float* W_msg = (const float*)d_in[4];
    const float* b_msg = (const float*)d_in[5];
    const float* Wz    = (const float*)d_in[6];
    const float* Uz    = (const float*)d_in[7];
    const float* bz    = (const float*)d_in[8];
    const float* Wr    = (const float*)d_in[9];
    const float* Ur    = (const float*)d_in[10];
    const float* br    = (const float*)d_in[11];
    const float* Wh    = (const float*)d_in[12];
    const float* Uh    = (const float*)d_in[13];
    const float* bh    = (const float*)d_in[14];
    const float* W_r1  = (const float*)d_in[15];
    const float* b_r1  = (const float*)d_in[16];
    const float* W_r2  = (const float*)d_in[17];
    const float* b_r2  = (const float*)d_in[18];
    float* out = (float*)d_out;

    float *h, *z, *jcz, *jcr, *jch, *t2;
    f16 *hP, *tP, *mP, *rhP, *daP, *wH, *wL;
    cudaGetSymbolAddress((void**)&h,   g_h);
    cudaGetSymbolAddress((void**)&z,   g_z);
    cudaGetSymbolAddress((void**)&jcz, g_jcz);
    cudaGetSymbolAddress((void**)&jcr, g_jcr);
    cudaGetSymbolAddress((void**)&jch, g_jch);
    cudaGetSymbolAddress((void**)&t2,  g_t2);
    cudaGetSymbolAddress((void**)&hP,  g_hP);
    cudaGetSymbolAddress((void**)&tP,  g_tP);
    cudaGetSymbolAddress((void**)&mP,  g_mP);
    cudaGetSymbolAddress((void**)&rhP, g_rhP);
    cudaGetSymbolAddress((void**)&daP, g_daP);
    cudaGetSymbolAddress((void**)&wH,  g_wH);
    cudaGetSymbolAddress((void**)&wL,  g_wL);

    f16 *hPh = hP, *hPl = hP + PLANE;
    f16 *tPh = tP, *tPl = tP + PLANE;
    f16 *mPh = mP, *mPl = mP + PLANE;
    f16 *rhPh = rhP, *rhPl = rhP + PLANE;
    f16 *daPh = daP, *daPl = daP + PLANE;

    static bool attr_done = false;
    if (!attr_done) {
        cudaFuncSetAttribute(tc_gemm<EPI_T,2>,   cudaFuncAttributeMaxDynamicSharedMemorySize, SMEM_BYTES);
        cudaFuncSetAttribute(tc_gemm<EPI_M,2>,   cudaFuncAttributeMaxDynamicSharedMemorySize, SMEM_BYTES);
        cudaFuncSetAttribute(tc_gemm<EPI_Z,1>,   cudaFuncAttributeMaxDynamicSharedMemorySize, SMEM_BYTES);
        cudaFuncSetAttribute(tc_gemm<EPI_R,1>,   cudaFuncAttributeMaxDynamicSharedMemorySize, SMEM_BYTES);
        cudaFuncSetAttribute(tc_gemm<EPI_GRU,2>, cudaFuncAttributeMaxDynamicSharedMemorySize, SMEM_BYTES);
        cudaFuncSetAttribute(tc_gemm<EPI_R1,2>,  cudaFuncAttributeMaxDynamicSharedMemorySize, SMEM_BYTES);
        cudaFuncSetAttribute(tc_gemm<EPI_R2,2>,  cudaFuncAttributeMaxDynamicSharedMemorySize, SMEM_BYTES);
        attr_done = true;
    }

    split_plain<<<PLANE/4/256, 256>>>(dads, PLANE/4, daPh, daPl);
    split_plain<<<65536/4/256, 256>>>(W_msg, 65536/4, wH + WOFF_MSG, wL + WOFF_MSG);
    split_plain<<<65536/4/256, 256>>>(W_r1,  65536/4, wH + WOFF_R1,  wL + WOFF_R1);
    split_plain<<<65536/4/256, 256>>>(W_r2,  65536/4, wH + WOFF_R2,  wL + WOFF_R2);
    build_zrB<<<262144/256, 256>>>(Wz, Wr, Uz, Ur, wH + WOFF_ZR, wL + WOFF_ZR);
    build_hB<<<131072/256, 256>>>(Wh, Uh, wH + WOFF_HB, wL + WOFF_HB);

    emb_kernel<<<ROWS, Hn>>>(jets, W_emb, b_emb, h, hPh, hPl);
    jc_kernel<<<ROWS, Hn>>>(jets, Wz, Wr, Wh, bz, br, bh, jcz, jcr, jch);

    dim3 grid2(2, ROWS/128);   // all GEMMs: 256 CTAs = one full wave at 2 CTA/SM
    for (int it = 0; it < N_ITERS; it++) {
        // t = h @ W_msg + b_msg   (2-pass)
        tc_gemm<EPI_T,2><<<grid2, 256, SMEM_BYTES>>>(
            hPh, hPl, nullptr, nullptr, wH + WOFF_MSG, wL + WOFF_MSG,
            256, 256, 0, b_msg, nullptr, nullptr, nullptr,
            nullptr, tPh, tPl);
        // m = tanh(dads @ t)   (2-pass: b_lo residuals have random sign -> cancellation)
        tc_gemm<EPI_M,2><<<grid2, 256, SMEM_BYTES>>>(
            daPh, daPl, nullptr, nullptr, tPh, tPl,
            256, 256, 1, nullptr, nullptr, nullptr, nullptr,
            nullptr, mPh, mPl);
        // z gate (1-pass fp16; sigmoid' + (h~-h) double damping)
        tc_gemm<EPI_Z,1><<<grid2, 256, SMEM_BYTES>>>(
            mPh, mPl, hPh, hPl, wH + WOFF_ZR, wL + WOFF_ZR,
            512, 512, 0, nullptr, jcz, nullptr, nullptr,
            z, nullptr, nullptr);
        // r gate -> rh planes (1-pass fp16)
        tc_gemm<EPI_R,1><<<grid2, 256, SMEM_BYTES>>>(
            mPh, mPl, hPh, hPl, wH + WOFF_ZR + 256, wL + WOFF_ZR + 256,
            512, 512, 0, nullptr, jcr, h, nullptr,
            nullptr, rhPh, rhPl);
        // GRU update (2-pass)
        tc_gemm<EPI_GRU,2><<<grid2, 256, SMEM_BYTES>>>(
            mPh, mPl, rhPh, rhPl, wH + WOFF_HB, wL + WOFF_HB,
            256, 512, 0, nullptr, jch, h, z,
            h, hPh, hPl);
    }

    tc_gemm<EPI_R1,2><<<grid2, 256, SMEM_BYTES>>>(
        hPh, hPl, nullptr, nullptr, wH + WOFF_R1, wL + WOFF_R1,
        256, 256, 0, b_r1, nullptr, nullptr, nullptr,
        nullptr, tPh, tPl);
    tc_gemm<EPI_R2,2><<<grid2, 256, SMEM_BYTES>>>(
        tPh, tPl, nullptr, nullptr, wH + WOFF_R2, wL + WOFF_R2,
        256, 256, 0, b_r2, nullptr, nullptr, nullptr,
        t2, nullptr, nullptr);
    reduce_kernel<<<Bn, 256>>>(t2, out);
}

// round 12
// speedup vs baseline: 1.8742x; 1.1104x over previous
#include <cuda_runtime.h>
#include <cuda_fp16.h>
#include <cstdint>
#include <math.h>

typedef __half f16;

// ---------------- problem dims ----------------
#define Bn 64
#define Nn 256
#define Fn 16
#define Hn 256
#define ROWS (Bn*Nn)          // 16384
#define N_ITERS 10
#define PLANE (ROWS*Hn)       // 4194304

// ---------------- scratch ----------------
__device__ float g_h  [PLANE];
__device__ float g_z  [PLANE];
__device__ float g_jcz[PLANE];
__device__ float g_jcr[PLANE];
__device__ float g_jch[PLANE];
__device__ float g_t2 [PLANE];
__device__ f16 g_hP [2*PLANE];
__device__ f16 g_tP [2*PLANE];
__device__ f16 g_mP [2*PLANE];
__device__ f16 g_rhP[2*PLANE];
__device__ f16 g_daP[2*PLANE];
#define WOFF_MSG 0
#define WOFF_ZR  65536
#define WOFF_HB  327680
#define WOFF_R1  458752
#define WOFF_R2  524288
#define WTOTAL   589824
__device__ f16 g_wH[WTOTAL];
__device__ f16 g_wL[WTOTAL];

__device__ __forceinline__ float sigf(float x) { return 1.0f / (1.0f + expf(-x)); }

__device__ __forceinline__ uint32_t smem_u32(const void* p) {
    return (uint32_t)__cvta_generic_to_shared(p);
}
#define CP16(dst, src) asm volatile("cp.async.cg.shared.global [%0], [%1], 16;" :: "r"(dst), "l"(src))
#define CP_COMMIT()    asm volatile("cp.async.commit_group;" ::: "memory")
#define CP_WAIT(n)     asm volatile("cp.async.wait_group %0;" :: "n"(n) : "memory")

__device__ __forceinline__ void split1(float v, f16& h, f16& l) {
    h = __float2half_rn(v);
    l = __float2half_rn(v - __half2float(h));
}
__device__ __forceinline__ void store_planes(f16* Ph, f16* Pl, size_t idx, float4 v) {
    __half2 h01 = __floats2half2_rn(v.x, v.y);
    __half2 h23 = __floats2half2_rn(v.z, v.w);
    float r0 = v.x - __low2float(h01), r1 = v.y - __high2float(h01);
    float r2 = v.z - __low2float(h23), r3 = v.w - __high2float(h23);
    __half2 l01 = __floats2half2_rn(r0, r1);
    __half2 l23 = __floats2half2_rn(r2, r3);
    uint2 hv, lv;
    hv.x = *(uint32_t*)&h01; hv.y = *(uint32_t*)&h23;
    lv.x = *(uint32_t*)&l01; lv.y = *(uint32_t*)&l23;
    *(uint2*)(Ph + idx) = hv;
    *(uint2*)(Pl + idx) = lv;
}
__device__ __forceinline__ void store_planes2(f16* Ph, f16* Pl, size_t idx, float2 v) {
    __half2 h = __floats2half2_rn(v.x, v.y);
    float r0 = v.x - __low2float(h), r1 = v.y - __high2float(h);
    __half2 l = __floats2half2_rn(r0, r1);
    *(uint32_t*)(Ph + idx) = *(uint32_t*)&h;
    *(uint32_t*)(Pl + idx) = *(uint32_t*)&l;
}
__device__ __forceinline__ void store_hi2(f16* Ph, size_t idx, float2 v) {
    __half2 h = __floats2half2_rn(v.x, v.y);
    *(uint32_t*)(Ph + idx) = *(uint32_t*)&h;
}

// ---------------- raw mma helpers ----------------
__device__ __forceinline__ void ldsm4(uint32_t addr, uint32_t& r0, uint32_t& r1, uint32_t& r2, uint32_t& r3) {
    asm volatile("ldmatrix.sync.aligned.m8n8.x4.shared.b16 {%0,%1,%2,%3}, [%4];"
                 : "=r"(r0), "=r"(r1), "=r"(r2), "=r"(r3) : "r"(addr));
}
__device__ __forceinline__ void ldsm4t(uint32_t addr, uint32_t& r0, uint32_t& r1, uint32_t& r2, uint32_t& r3) {
    asm volatile("ldmatrix.sync.aligned.m8n8.x4.trans.shared.b16 {%0,%1,%2,%3}, [%4];"
                 : "=r"(r0), "=r"(r1), "=r"(r2), "=r"(r3) : "r"(addr));
}
__device__ __forceinline__ void mma16816(float* d, const uint32_t* a, const uint32_t* b) {
    asm volatile("mma.sync.aligned.m16n8k16.row.col.f32.f16.f16.f32 "
                 "{%0,%1,%2,%3}, {%4,%5,%6,%7}, {%8,%9}, {%0,%1,%2,%3};"
                 : "+f"(d[0]), "+f"(d[1]), "+f"(d[2]), "+f"(d[3])
                 : "r"(a[0]), "r"(a[1]), "r"(a[2]), "r"(a[3]), "r"(b[0]), "r"(b[1]));
}

// ---------------- GEMM: 128x128 tile, raw mma, fp16 1/2/3-pass split ------
enum { EPI_T = 0, EPI_M, EPI_Z, EPI_R, EPI_GRU, EPI_R1, EPI_R2 };

#define STAGES 3
#define LDA 40
#define LDB 136
#define AHI_OFF 0
#define ALO_OFF 10240
#define BHI_OFF 20480
#define BLO_OFF 29184
#define STAGE_BYTES 37888
#define SMEM_BYTES (STAGES*STAGE_BYTES)   // 113664

template<int EPI, int PASSES>
__global__ void __launch_bounds__(256, 2)
tc_gemm(const f16* __restrict__ A0h, const f16* __restrict__ A0l,
        const f16* __restrict__ A1h, const f16* __restrict__ A1l,
        const f16* __restrict__ Bh,  const f16* __restrict__ Bl,
        int NB, int K, int batched,
        const float* __restrict__ bias,
        const float* __restrict__ jc,
        const float* __restrict__ Hb,  const float* __restrict__ Zb,
        float* Cf, f16* Ch, f16* Cl)
{
    extern __shared__ char sm[];
    const uint32_t smaddr = smem_u32(sm);

    const int tid = threadIdx.x, wid = tid >> 5, lane = tid & 31;
    const int bn = blockIdx.x * 128, bm = blockIdx.y * 128;
    const int warp_m = wid >> 2;
    const int warp_n = wid & 3;

    int am = bm;
    size_t aoff = 0, boff = 0;
    if (batched) {
        const int b = bm >> 8;
        aoff = (size_t)b * (Nn * Hn);
        boff = (size_t)b * (Nn * Hn);
        am = bm & (Nn - 1);
    }

    const int NC = K >> 5;

    auto issue = [&](int kb) {
        const int buf = kb % STAGES;
        const uint32_t sb = smaddr + buf * STAGE_BYTES;
        const int kk = (kb & 7) * 32;
        const f16 *ah, *al; int arow;
        if (kb < 8) { ah = A0h + aoff; al = A0l + aoff; arow = am; }
        else        { ah = A1h;        al = A1l;        arow = bm; }
        #pragma unroll
        for (int i = 0; i < 2; i++) {
            const int c = tid + i * 256;
            {
                const int r = c >> 2, c8 = (c & 3) * 8;
                const f16* s1 = ah + (size_t)(arow + r) * Hn + kk + c8;
                const uint32_t d = sb + AHI_OFF + (uint32_t)(r * LDA + c8) * 2;
                CP16(d, s1);
                if (PASSES >= 2) {
                    const f16* s2 = al + (size_t)(arow + r) * Hn + kk + c8;
                    CP16(d + (ALO_OFF - AHI_OFF), s2);
                }
            }
            {
                const int r = c >> 4, c8 = (c & 15) * 8;
                const f16* s1 = Bh + boff + (size_t)(kb * 32 + r) * NB + bn + c8;
                const uint32_t d = sb + BHI_OFF + (uint32_t)(r * LDB + c8) * 2;
                CP16(d, s1);
                if (PASSES == 3) {
                    const f16* s2 = Bl + boff + (size_t)(kb * 32 + r) * NB + bn + c8;
                    CP16(d + (BLO_OFF - BHI_OFF), s2);
                }
            }
        }
    };

    float acc[4][4][4];
    #pragma unroll
    for (int mi = 0; mi < 4; mi++)
        #pragma unroll
        for (int nj = 0; nj < 4; nj++)
            #pragma unroll
            for (int q = 0; q < 4; q++) acc[mi][nj][q] = 0.0f;

    const uint32_t a_lrow = (uint32_t)(lane & 15);
    const uint32_t a_lcol = (uint32_t)((lane >> 4) << 3);
    const uint32_t b_lrow = (uint32_t)(lane & 15);
    const uint32_t b_lcol = (uint32_t)((lane >> 4) << 3);

    issue(0); CP_COMMIT();
    if (NC > 1) issue(1);
    CP_COMMIT();

    for (int kb = 0; kb < NC; kb++) {
        CP_WAIT(1);
        __syncthreads();

        if (kb + STAGES - 1 < NC) issue(kb + STAGES - 1);
        CP_COMMIT();

        const uint32_t sb = smaddr + (kb % STAGES) * STAGE_BYTES;

        #pragma unroll
        for (int kk = 0; kk < 2; kk++) {
            const uint32_t brow = (uint32_t)(kk * 16) + b_lrow;
            const uint32_t bcol0 = (uint32_t)(warp_n * 32) + b_lcol;
            uint32_t bfr[8];
            {   // B_hi
                const uint32_t ba = sb + BHI_OFF + (brow * LDB + bcol0) * 2;
                ldsm4t(ba,      bfr[0], bfr[1], bfr[2], bfr[3]);
                ldsm4t(ba + 32, bfr[4], bfr[5], bfr[6], bfr[7]);
            }
            const uint32_t arow0 = (uint32_t)(warp_m * 64) + a_lrow;
            const uint32_t acol = (uint32_t)(kk * 16) + a_lcol;
            // ---- pass 1: A_hi x B_hi ----
            #pragma unroll
            for (int mi = 0; mi < 4; mi++) {
                uint32_t a[4];
                ldsm4(sb + AHI_OFF + ((arow0 + mi * 16) * LDA + acol) * 2, a[0], a[1], a[2], a[3]);
                #pragma unroll
                for (int nj = 0; nj < 4; nj++) mma16816(acc[mi][nj], a, &bfr[nj * 2]);
            }
            // ---- pass 2: A_lo x B_hi ----
            if (PASSES >= 2) {
                #pragma unroll
                for (int mi = 0; mi < 4; mi++) {
                    uint32_t a[4];
                    ldsm4(sb + ALO_OFF + ((arow0 + mi * 16) * LDA + acol) * 2, a[0], a[1], a[2], a[3]);
                    #pragma unroll
                    for (int nj = 0; nj < 4; nj++) mma16816(acc[mi][nj], a, &bfr[nj * 2]);
                }
            }
            // ---- pass 3: A_hi x B_lo ----
            if (PASSES == 3) {
                const uint32_t ba = sb + BLO_OFF + (brow * LDB + bcol0) * 2;
                ldsm4t(ba,      bfr[0], bfr[1], bfr[2], bfr[3]);
                ldsm4t(ba + 32, bfr[4], bfr[5], bfr[6], bfr[7]);
                #pragma unroll
                for (int mi = 0; mi < 4; mi++) {
                    uint32_t a[4];
                    ldsm4(sb + AHI_OFF + ((arow0 + mi * 16) * LDA + acol) * 2, a[0], a[1], a[2], a[3]);
                    #pragma unroll
                    for (int nj = 0; nj < 4; nj++) mma16816(acc[mi][nj], a, &bfr[nj * 2]);
                }
            }
        }
    }

    // ---------------- register-direct epilogue ----------------
    const int r_in = lane >> 2;
    const int c_in = (lane & 3) * 2;

    #pragma unroll
    for (int mi = 0; mi < 4; mi++) {
        #pragma unroll
        for (int nj = 0; nj < 4; nj++) {
            #pragma unroll
            for (int half = 0; half < 2; half++) {
                const int row = bm + warp_m * 64 + mi * 16 + r_in + half * 8;
                const int col = bn + warp_n * 32 + nj * 8 + c_in;
                float2 v = make_float2(acc[mi][nj][half * 2], acc[mi][nj][half * 2 + 1]);
                const size_t idx = (size_t)row * Hn + col;

                if (EPI == EPI_T) {
                    // t used only via fp16 hi by 1-pass M -> hi plane only
                    float2 bv = *(const float2*)(bias + col);
                    v.x += bv.x; v.y += bv.y;
                    store_hi2(Ch, idx, v);
                } else if (EPI == EPI_R1) {
                    float2 bv = *(const float2*)(bias + col);
                    v.x = tanhf(v.x + bv.x); v.y = tanhf(v.y + bv.y);
                    store_planes2(Ch, Cl, idx, v);
                } else if (EPI == EPI_M) {
                    v.x = tanhf(v.x); v.y = tanhf(v.y);
                    store_planes2(Ch, Cl, idx, v);     // GRU (2-pass) needs m lo
                } else if (EPI == EPI_Z) {
                    float2 jv = *(const float2*)(jc + idx);
                    v.x = sigf(v.x + jv.x); v.y = sigf(v.y + jv.y);
                    *(float2*)(Cf + idx) = v;
                } else if (EPI == EPI_R) {
                    float2 jv = *(const float2*)(jc + idx);
                    float2 hv = *(const float2*)(Hb + idx);
                    v.x = sigf(v.x + jv.x) * hv.x;
                    v.y = sigf(v.y + jv.y) * hv.y;
                    store_planes2(Ch, Cl, idx, v);     // GRU (2-pass) needs rh lo
                } else if (EPI == EPI_GRU) {
                    float2 jv = *(const float2*)(jc + idx);
                    float2 hv = *(const float2*)(Hb + idx);
                    float2 zv = *(const float2*)(Zb + idx);
                    float t0 = tanhf(v.x + jv.x), t1 = tanhf(v.y + jv.y);
                    v.x = hv.x + zv.x * (t0 - hv.x);
                    v.y = hv.y + zv.y * (t1 - hv.y);
                    *(float2*)(Cf + idx) = v;
                    store_hi2(Ch, idx, v);             // h lo plane has no consumer
                } else if (EPI == EPI_R2) {
                    float2 bv = *(const float2*)(bias + col);
                    v.x += bv.x; v.y += bv.y;
                    *(float2*)(Cf + idx) = v;
                }
            }
        }
    }
}

// ---------------- split / build kernels ----------------
__global__ void split_plain(const float* __restrict__ src, int n4, f16* __restrict__ hi, f16* __restrict__ lo)
{
    const int i = blockIdx.x * 256 + threadIdx.x;
    if (i < n4) {
        float4 v = *(const float4*)(src + i * 4);
        store_planes(hi, lo, (size_t)i * 4, v);
    }
}

__global__ void build_zrB(const float* __restrict__ Wz, const float* __restrict__ Wr,
                          const float* __restrict__ Uz, const float* __restrict__ Ur,
                          f16* __restrict__ hi, f16* __restrict__ lo)
{
    const int i = blockIdx.x * 256 + threadIdx.x;
    const int k = i >> 9, c = i & 511;
    float v;
    if (k < 256) v = (c < 256) ? Wz[k * Hn + c] : Wr[k * Hn + (c - 256)];
    else         v = (c < 256) ? Uz[(k - 256) * Hn + c] : Ur[(k - 256) * Hn + (c - 256)];
    f16 h, l; split1(v, h, l);
    hi[i] = h; lo[i] = l;
}

__global__ void build_hB(const float* __restrict__ Wh, const float* __restrict__ Uh,
                         f16* __restrict__ hi, f16* __restrict__ lo)
{
    const int i = blockIdx.x * 256 + threadIdx.x;
    const int k = i >> 8, c = i & 255;
    float v = (k < 256) ? Wh[k * Hn + c] : Uh[(k - 256) * Hn + c];
    f16 h, l; split1(v, h, l);
    hi[i] = h; lo[i] = l;
}

// ---------------- small kernels ----------------
__global__ void emb_kernel(const float* __restrict__ jets, const float* __restrict__ W_emb,
                           const float* __restrict__ b_emb, float* __restrict__ h,
                           f16* __restrict__ hPh, f16* __restrict__ hPl)
{
    const int row = blockIdx.x, j = threadIdx.x;
    __shared__ float sj[Fn];
    if (j < Fn) sj[j] = jets[(size_t)row * Fn + j];
    __syncthreads();
    float acc = b_emb[j];
    #pragma unroll
    for (int k = 0; k < Fn; k++) acc = fmaf(sj[k], W_emb[k * Hn + j], acc);
    const float v = tanhf(acc);
    const size_t idx = (size_t)row * Hn + j;
    h[idx] = v;
    hPh[idx] = __float2half_rn(v);    // lo plane unused by consumers
}

__global__ void jc_kernel(const float* __restrict__ jets,
                          const float* __restrict__ Wz, const float* __restrict__ Wr,
                          const float* __restrict__ Wh,
                          const float* __restrict__ bz, const float* __restrict__ br,
                          const float* __restrict__ bh,
                          float* jcz, float* jcr, float* jch)
{
    const int row = blockIdx.x, j = threadIdx.x;
    __shared__ float sj[Fn];
    if (j < Fn) sj[j] = jets[(size_t)row * Fn + j];
    __syncthreads();
    float az = bz[j], ar = br[j], ah = bh[j];
    #pragma unroll
    for (int k = 0; k < Fn; k++) {
        const float s = sj[k];
        const int widx = (Hn + k) * Hn + j;
        az = fmaf(s, Wz[widx], az);
        ar = fmaf(s, Wr[widx], ar);
        ah = fmaf(s, Wh[widx], ah);
    }
    const size_t idx = (size_t)row * Hn + j;
    jcz[idx] = az; jcr[idx] = ar; jch[idx] = ah;
}

__global__ void reduce_kernel(const float* __restrict__ t2, float* __restrict__ out)
{
    const int idx = blockIdx.x * blockDim.x + threadIdx.x;
    const int b = idx >> 8, j = idx & 255;
    const float* p = t2 + (size_t)b * (Nn * Hn) + j;
    float acc = 0.0f;
    for (int n = 0; n < Nn; n++) acc += p[(size_t)n * Hn];
    out[idx] = acc;
}

// ---------------- launch ----------------
extern "C" void kernel_launch(void* const* d_in, const int* in_sizes, int n_in,
                              void* d_out, int out_size)
{
    const float* jets  = (const float*)d_in[0];
    const float* dads  = (const float*)d_in[1];
    const float* W_emb = (const float*)d_in[2];
    const float* b_emb = (const float*)d_in[3];
    const float* W_msg = (const float*)d_in[4];
    const float* b_msg = (const float*)d_in[5];
    const float* Wz    = (const float*)d_in[6];
    const float* Uz    = (const float*)d_in[7];
    const float* bz    = (const float*)d_in[8];
    const float* Wr    = (const float*)d_in[9];
    const float* Ur    = (const float*)d_in[10];
    const float* br    = (const float*)d_in[11];
    const float* Wh    = (const float*)d_in[12];
    const float* Uh    = (const float*)d_in[13];
    const float* bh    = (const float*)d_in[14];
    const float* W_r1  = (const float*)d_in[15];
    const float* b_r1  = (const float*)d_in[16];
    const float* W_r2  = (const float*)d_in[17];
    const float* b_r2  = (const float*)d_in[18];
    float* out = (float*)d_out;

    float *h, *z, *jcz, *jcr, *jch, *t2;
    f16 *hP, *tP, *mP, *rhP, *daP, *wH, *wL;
    cudaGetSymbolAddress((void**)&h,   g_h);
    cudaGetSymbolAddress((void**)&z,   g_z);
    cudaGetSymbolAddress((void**)&jcz, g_jcz);
    cudaGetSymbolAddress((void**)&jcr, g_jcr);
    cudaGetSymbolAddress((void**)&jch, g_jch);
    cudaGetSymbolAddress((void**)&t2,  g_t2);
    cudaGetSymbolAddress((void**)&hP,  g_hP);
    cudaGetSymbolAddress((void**)&tP,  g_tP);
    cudaGetSymbolAddress((void**)&mP,  g_mP);
    cudaGetSymbolAddress((void**)&rhP, g_rhP);
    cudaGetSymbolAddress((void**)&daP, g_daP);
    cudaGetSymbolAddress((void**)&wH,  g_wH);
    cudaGetSymbolAddress((void**)&wL,  g_wL);

    f16 *hPh = hP, *hPl = hP + PLANE;
    f16 *tPh = tP, *tPl = tP + PLANE;
    f16 *mPh = mP, *mPl = mP + PLANE;
    f16 *rhPh = rhP, *rhPl = rhP + PLANE;
    f16 *daPh = daP, *daPl = daP + PLANE;

    static bool attr_done = false;
    if (!attr_done) {
        cudaFuncSetAttribute(tc_gemm<EPI_T,1>,   cudaFuncAttributeMaxDynamicSharedMemorySize, SMEM_BYTES);
        cudaFuncSetAttribute(tc_gemm<EPI_M,1>,   cudaFuncAttributeMaxDynamicSharedMemorySize, SMEM_BYTES);
        cudaFuncSetAttribute(tc_gemm<EPI_Z,1>,   cudaFuncAttributeMaxDynamicSharedMemorySize, SMEM_BYTES);
        cudaFuncSetAttribute(tc_gemm<EPI_R,1>,   cudaFuncAttributeMaxDynamicSharedMemorySize, SMEM_BYTES);
        cudaFuncSetAttribute(tc_gemm<EPI_GRU,2>, cudaFuncAttributeMaxDynamicSharedMemorySize, SMEM_BYTES);
        cudaFuncSetAttribute(tc_gemm<EPI_R1,2>,  cudaFuncAttributeMaxDynamicSharedMemorySize, SMEM_BYTES);
        cudaFuncSetAttribute(tc_gemm<EPI_R2,2>,  cudaFuncAttributeMaxDynamicSharedMemorySize, SMEM_BYTES);
        attr_done = true;
    }

    split_plain<<<PLANE/4/256, 256>>>(dads, PLANE/4, daPh, daPl);
    split_plain<<<65536/4/256, 256>>>(W_msg, 65536/4, wH + WOFF_MSG, wL + WOFF_MSG);
    split_plain<<<65536/4/256, 256>>>(W_r1,  65536/4, wH + WOFF_R1,  wL + WOFF_R1);
    split_plain<<<65536/4/256, 256>>>(W_r2,  65536/4, wH + WOFF_R2,  wL + WOFF_R2);
    build_zrB<<<262144/256, 256>>>(Wz, Wr, Uz, Ur, wH + WOFF_ZR, wL + WOFF_ZR);
    build_hB<<<131072/256, 256>>>(Wh, Uh, wH + WOFF_HB, wL + WOFF_HB);

    emb_kernel<<<ROWS, Hn>>>(jets, W_emb, b_emb, h, hPh, hPl);
    jc_kernel<<<ROWS, Hn>>>(jets, Wz, Wr, Wh, bz, br, bh, jcz, jcr, jch);

    dim3 grid2(2, ROWS/128);   // every GEMM: 256 CTAs = one full wave at 2 CTA/SM
    for (int it = 0; it < N_ITERS; it++) {
        // t = h @ W_msg + b_msg   (1-pass; t error washes out through dads averaging)
        tc_gemm<EPI_T,1><<<grid2, 256, SMEM_BYTES>>>(
            hPh, hPl, nullptr, nullptr, wH + WOFF_MSG, wL + WOFF_MSG,
            256, 256, 0, b_msg, nullptr, nullptr, nullptr,
            nullptr, tPh, tPl);
        // m = tanh(dads @ t)   (1-pass; dads entries ~1/N -> negligible lo term)
        tc_gemm<EPI_M,1><<<grid2, 256, SMEM_BYTES>>>(
            daPh, daPl, nullptr, nullptr, tPh, tPl,
            256, 256, 1, nullptr, nullptr, nullptr, nullptr,
            nullptr, mPh, mPl);
        // z gate (1-pass)
        tc_gemm<EPI_Z,1><<<grid2, 256, SMEM_BYTES>>>(
            mPh, mPl, hPh, hPl, wH + WOFF_ZR, wL + WOFF_ZR,
            512, 512, 0, nullptr, jcz, nullptr, nullptr,
            z, nullptr, nullptr);
        // r gate -> rh planes (1-pass)
        tc_gemm<EPI_R,1><<<grid2, 256, SMEM_BYTES>>>(
            mPh, mPl, hPh, hPl, wH + WOFF_ZR + 256, wL + WOFF_ZR + 256,
            512, 512, 0, nullptr, jcr, h, nullptr,
            nullptr, rhPh, rhPl);
        // GRU update (2-pass; h accumulates across iterations)
        tc_gemm<EPI_GRU,2><<<grid2, 256, SMEM_BYTES>>>(
            mPh, mPl, rhPh, rhPl, wH + WOFF_HB, wL + WOFF_HB,
            256, 512, 0, nullptr, jch, h, z,
            h, hPh, hPl);
    }

    tc_gemm<EPI_R1,2><<<grid2, 256, SMEM_BYTES>>>(
        hPh, hPl, nullptr, nullptr, wH + WOFF_R1, wL + WOFF_R1,
        256, 256, 0, b_r1, nullptr, nullptr, nullptr,
        nullptr, tPh, tPl);
    tc_gemm<EPI_R2,2><<<grid2, 256, SMEM_BYTES>>>(
        tPh, tPl, nullptr, nullptr, wH + WOFF_R2, wL + WOFF_R2,
        256, 256, 0, b_r2, nullptr, nullptr, nullptr,
        t2, nullptr, nullptr);
    reduce_kernel<<<Bn, 256>>>(t2, out);
}